// round 1
// baseline (speedup 1.0000x reference)
#include <cuda_runtime.h>
#include <math.h>

#define BATCH   8
#define NTOK    1025
#define DMODEL  768
#define NH      12
#define HDIM    64
#define NPATCH  1024
#define QKVW    (3*DMODEL)          // 2304
#define EPS     1e-5f
#define LOG2E   1.4426950408889634f
#define SCALE   0.03608439182435161f   // 768^-0.5
#define MTOT    (BATCH*NTOK)        // 8200

// ---------------- scratch (device globals; no allocation) ----------------
__device__ float g_xnorm[(size_t)MTOT * DMODEL];       // 25.2 MB
__device__ float g_qkv  [(size_t)MTOT * QKVW];         // 75.6 MB
__device__ float g_ctx  [(size_t)MTOT * DMODEL];       // 25.2 MB

// ---------------- block reduction helpers (256 threads) ----------------
__device__ __forceinline__ float blockReduceSum(float v, float* red) {
    #pragma unroll
    for (int o = 16; o > 0; o >>= 1) v += __shfl_xor_sync(0xffffffffu, v, o);
    int lane = threadIdx.x & 31, w = threadIdx.x >> 5;
    __syncthreads();
    if (lane == 0) red[w] = v;
    __syncthreads();
    if (threadIdx.x == 0) {
        float s = 0.f;
        #pragma unroll
        for (int i = 0; i < 8; i++) s += red[i];
        red[0] = s;
    }
    __syncthreads();
    return red[0];
}

__device__ __forceinline__ float blockReduceMax(float v, float* red) {
    #pragma unroll
    for (int o = 16; o > 0; o >>= 1) v = fmaxf(v, __shfl_xor_sync(0xffffffffu, v, o));
    int lane = threadIdx.x & 31, w = threadIdx.x >> 5;
    __syncthreads();
    if (lane == 0) red[w] = v;
    __syncthreads();
    if (threadIdx.x == 0) {
        float s = -1e30f;
        #pragma unroll
        for (int i = 0; i < 8; i++) s = fmaxf(s, red[i]);
        red[0] = s;
    }
    __syncthreads();
    return red[0];
}

// ---------------- LayerNorm: one row (768) per block, 256 threads ----------------
__global__ __launch_bounds__(256) void ln_kernel(const float* __restrict__ x,
                                                 const float* __restrict__ w,
                                                 const float* __restrict__ bias) {
    int row = blockIdx.x;
    const float* xr = x + (size_t)row * DMODEL;
    int t = threadIdx.x;
    float v[3];
    float s = 0.f, sq = 0.f;
    #pragma unroll
    for (int i = 0; i < 3; i++) {
        v[i] = xr[t + i * 256];
        s += v[i];
        sq += v[i] * v[i];
    }
    __shared__ float red[32];
    __shared__ float stats[2];
    #pragma unroll
    for (int o = 16; o > 0; o >>= 1) {
        s  += __shfl_xor_sync(0xffffffffu, s, o);
        sq += __shfl_xor_sync(0xffffffffu, sq, o);
    }
    int lane = t & 31, wp = t >> 5;
    if (lane == 0) { red[wp] = s; red[8 + wp] = sq; }
    __syncthreads();
    if (t == 0) {
        float a = 0.f, b2 = 0.f;
        #pragma unroll
        for (int i = 0; i < 8; i++) { a += red[i]; b2 += red[8 + i]; }
        stats[0] = a; stats[1] = b2;
    }
    __syncthreads();
    float mean = stats[0] * (1.f / DMODEL);
    float var  = stats[1] * (1.f / DMODEL) - mean * mean;
    float inv  = rsqrtf(var + EPS);
    float* o = g_xnorm + (size_t)row * DMODEL;
    #pragma unroll
    for (int i = 0; i < 3; i++) {
        int c = t + i * 256;
        o[c] = (v[i] - mean) * inv * w[c] + bias[c];
    }
}

// ---------------- SGEMM: C[M,N] = A[M,K] @ B[K,N] (+bias) ----------------
// BM=128, BN=64, BK=16, 256 threads, 8x4 micro-tile.
// SEL=0: A=g_xnorm, C=g_qkv (no bias). SEL=1: A=g_ctx, C=Cext (+bias).
template<int SEL>
__global__ __launch_bounds__(256) void sgemm_kernel(const float* __restrict__ Bm,
                                                    const float* __restrict__ bias,
                                                    float* __restrict__ Cext,
                                                    int M, int N, int K) {
    const float* A = (SEL == 0) ? g_xnorm : g_ctx;
    float* C       = (SEL == 0) ? g_qkv   : Cext;

    __shared__ float As[16][128];
    __shared__ float Bs[16][64];

    int tid = threadIdx.x;
    int tx = tid & 15, ty = tid >> 4;
    int n0 = blockIdx.x * 64;
    int m0 = blockIdx.y * 128;

    float acc[8][4];
    #pragma unroll
    for (int i = 0; i < 8; i++)
        #pragma unroll
        for (int j = 0; j < 4; j++) acc[i][j] = 0.f;

    for (int kb = 0; kb < K; kb += 16) {
        // load A tile (transposed into smem)
        #pragma unroll
        for (int l = 0; l < 2; l++) {
            int f = tid + l * 256;
            int r = f >> 2, c4 = f & 3;
            float4 v = make_float4(0.f, 0.f, 0.f, 0.f);
            if (m0 + r < M)
                v = *(const float4*)(A + (size_t)(m0 + r) * K + kb + c4 * 4);
            As[c4 * 4 + 0][r] = v.x;
            As[c4 * 4 + 1][r] = v.y;
            As[c4 * 4 + 2][r] = v.z;
            As[c4 * 4 + 3][r] = v.w;
        }
        // load B tile
        {
            int kr = tid >> 4, c4 = tid & 15;
            float4 v = *(const float4*)(Bm + (size_t)(kb + kr) * N + n0 + c4 * 4);
            *(float4*)&Bs[kr][c4 * 4] = v;
        }
        __syncthreads();

        #pragma unroll
        for (int k = 0; k < 16; k++) {
            float a[8], b[4];
            *(float4*)&a[0] = *(const float4*)&As[k][ty * 8];
            *(float4*)&a[4] = *(const float4*)&As[k][ty * 8 + 4];
            *(float4*)&b[0] = *(const float4*)&Bs[k][tx * 4];
            #pragma unroll
            for (int i = 0; i < 8; i++)
                #pragma unroll
                for (int j = 0; j < 4; j++)
                    acc[i][j] += a[i] * b[j];
        }
        __syncthreads();
    }

    float bv0 = 0.f, bv1 = 0.f, bv2 = 0.f, bv3 = 0.f;
    if (SEL == 1) {
        float4 bb = *(const float4*)(bias + n0 + tx * 4);
        bv0 = bb.x; bv1 = bb.y; bv2 = bb.z; bv3 = bb.w;
    }
    #pragma unroll
    for (int i = 0; i < 8; i++) {
        int r = m0 + ty * 8 + i;
        if (r < M) {
            float4 v;
            v.x = acc[i][0] + bv0;
            v.y = acc[i][1] + bv1;
            v.z = acc[i][2] + bv2;
            v.w = acc[i][3] + bv3;
            *(float4*)(C + (size_t)r * N + n0 + tx * 4) = v;
        }
    }
}

// ---------------- Flash attention for query rows 1..1024 ----------------
// grid (32 qtiles, 96 bh), 256 threads. thread = (row = t/8, dlane = t%8).
// Thread owns dims d = dlane + 8*i (i<8) and computes keys j = dlane + 8*i (i<4).
__global__ __launch_bounds__(256) void attn_kernel() {
    int qt = blockIdx.x;
    int bh = blockIdx.y;
    int b = bh / NH, h = bh % NH;

    __shared__ float Qs[32][65];
    __shared__ float Ks[32][65];
    __shared__ float Vs[32][65];
    __shared__ float Ps[32][65];

    int tid = threadIdx.x;
    int row = tid >> 3, dl = tid & 7;
    size_t base = (size_t)b * NTOK * QKVW;

    // load Q tile (rows 1 + qt*32 + r)
    #pragma unroll
    for (int l = 0; l < 2; l++) {
        int f = tid + l * 256;
        int r = f >> 4, c4 = f & 15;
        int qrow = 1 + qt * 32 + r;
        float4 v = *(const float4*)(g_qkv + base + (size_t)qrow * QKVW + h * 64 + c4 * 4);
        Qs[r][c4 * 4 + 0] = v.x;
        Qs[r][c4 * 4 + 1] = v.y;
        Qs[r][c4 * 4 + 2] = v.z;
        Qs[r][c4 * 4 + 3] = v.w;
    }

    float m = -1e30f, lsum = 0.f;
    float O[8];
    #pragma unroll
    for (int i = 0; i < 8; i++) O[i] = 0.f;

    for (int c = 0; c < 33; c++) {
        int j0 = c * 32;
        __syncthreads();   // previous PV readers done before reload
        // load K,V chunk
        #pragma unroll
        for (int l = 0; l < 2; l++) {
            int f = tid + l * 256;
            int r = f >> 4, c4 = f & 15;
            int j = j0 + r;
            float4 kv = make_float4(0.f, 0.f, 0.f, 0.f);
            float4 vv = make_float4(0.f, 0.f, 0.f, 0.f);
            if (j < NTOK) {
                const float* p = g_qkv + base + (size_t)j * QKVW + h * 64;
                kv = *(const float4*)(p + DMODEL     + c4 * 4);
                vv = *(const float4*)(p + 2 * DMODEL + c4 * 4);
            }
            Ks[r][c4 * 4 + 0] = kv.x; Ks[r][c4 * 4 + 1] = kv.y;
            Ks[r][c4 * 4 + 2] = kv.z; Ks[r][c4 * 4 + 3] = kv.w;
            Vs[r][c4 * 4 + 0] = vv.x; Vs[r][c4 * 4 + 1] = vv.y;
            Vs[r][c4 * 4 + 2] = vv.z; Vs[r][c4 * 4 + 3] = vv.w;
        }
        __syncthreads();

        // S = Q Kᵀ for this thread's 4 keys
        float s[4] = {0.f, 0.f, 0.f, 0.f};
        #pragma unroll
        for (int k = 0; k < 64; k++) {
            float qv = Qs[row][k];
            #pragma unroll
            for (int i = 0; i < 4; i++) s[i] += qv * Ks[dl + 8 * i][k];
        }
        #pragma unroll
        for (int i = 0; i < 4; i++) {
            s[i] *= SCALE;
            if (j0 + dl + 8 * i >= NTOK) s[i] = -1e30f;
        }
        // online softmax: max over row's 32 keys (8-lane group reduce)
        float cmax = fmaxf(fmaxf(s[0], s[1]), fmaxf(s[2], s[3]));
        cmax = fmaxf(cmax, __shfl_xor_sync(0xffffffffu, cmax, 1));
        cmax = fmaxf(cmax, __shfl_xor_sync(0xffffffffu, cmax, 2));
        cmax = fmaxf(cmax, __shfl_xor_sync(0xffffffffu, cmax, 4));
        float mnew = fmaxf(m, cmax);
        float fac = exp2f((m - mnew) * LOG2E);
        float p[4], psum = 0.f;
        #pragma unroll
        for (int i = 0; i < 4; i++) {
            p[i] = exp2f((s[i] - mnew) * LOG2E);
            psum += p[i];
        }
        psum += __shfl_xor_sync(0xffffffffu, psum, 1);
        psum += __shfl_xor_sync(0xffffffffu, psum, 2);
        psum += __shfl_xor_sync(0xffffffffu, psum, 4);
        lsum = lsum * fac + psum;
        m = mnew;
        #pragma unroll
        for (int i = 0; i < 8; i++) O[i] *= fac;
        #pragma unroll
        for (int i = 0; i < 4; i++) Ps[row][dl + 8 * i] = p[i];
        __syncwarp();
        // O += P @ V
        #pragma unroll
        for (int j = 0; j < 32; j++) {
            float pv = Ps[row][j];
            #pragma unroll
            for (int i = 0; i < 8; i++) O[i] += pv * Vs[j][dl + 8 * i];
        }
        __syncwarp();
    }

    float invl = 1.f / lsum;
    int qrow = 1 + qt * 32 + row;
    float* o = g_ctx + ((size_t)b * NTOK + qrow) * DMODEL + h * 64;
    #pragma unroll
    for (int i = 0; i < 8; i++) o[dl + 8 * i] = O[i] * invl;
}

// ---------------- CLS row (query row 0): 96 blocks, 256 threads ----------------
__global__ __launch_bounds__(256) void cls_kernel(const float* __restrict__ canny,
                                                  const float* __restrict__ noise) {
    int bh = blockIdx.x;
    int b = bh / NH, h = bh % NH;
    __shared__ float sm[NTOK];
    __shared__ float q0[64];
    __shared__ float red[32];
    __shared__ float part[4][64];
    int tid = threadIdx.x;
    size_t base = (size_t)b * NTOK * QKVW;

    if (tid < 64) q0[tid] = g_qkv[base + h * 64 + tid];
    __syncthreads();

    // scores s_j = q0 . k_j * scale
    for (int j = tid; j < NTOK; j += 256) {
        const float* kp = g_qkv + base + (size_t)j * QKVW + DMODEL + h * 64;
        float dot = 0.f;
        #pragma unroll
        for (int c4 = 0; c4 < 16; c4++) {
            float4 kv = *(const float4*)(kp + c4 * 4);
            dot += q0[c4 * 4 + 0] * kv.x + q0[c4 * 4 + 1] * kv.y
                 + q0[c4 * 4 + 2] * kv.z + q0[c4 * 4 + 3] * kv.w;
        }
        sm[j] = dot * SCALE;
    }
    __syncthreads();

    // pass A: max over patch scores; canny/noise sums
    float mx = -1e30f, cs = 0.f, ns = 0.f;
    for (int j = tid; j < NPATCH; j += 256) {
        mx = fmaxf(mx, sm[j + 1]);
        cs += canny[(size_t)b * NPATCH + j] + 1.f;
        ns += noise[(size_t)b * NPATCH + j];
    }
    mx = blockReduceMax(mx, red);
    cs = blockReduceSum(cs, red);
    ns = blockReduceSum(ns, red);
    float se = 0.f;
    for (int j = tid; j < NPATCH; j += 256) se += exp2f((sm[j + 1] - mx) * LOG2E);
    se = blockReduceSum(se, red);
    float inv_se = 1.f / se, inv_cs = 1.f / cs, inv_ns = 1.f / ns;
    for (int j = tid; j < NPATCH; j += 256) {
        float a = exp2f((sm[j + 1] - mx) * LOG2E) * inv_se;
        sm[j + 1] = a + (canny[(size_t)b * NPATCH + j] + 1.f) * inv_cs
                      + noise[(size_t)b * NPATCH + j] * inv_ns;
    }
    __syncthreads();

    // second softmax over all 1025
    float mx2 = -1e30f;
    for (int j = tid; j < NTOK; j += 256) mx2 = fmaxf(mx2, sm[j]);
    mx2 = blockReduceMax(mx2, red);
    float se2 = 0.f;
    for (int j = tid; j < NTOK; j += 256) se2 += exp2f((sm[j] - mx2) * LOG2E);
    se2 = blockReduceSum(se2, red);
    float inv2 = 1.f / se2;
    for (int j = tid; j < NTOK; j += 256) sm[j] = exp2f((sm[j] - mx2) * LOG2E) * inv2;
    __syncthreads();

    // out = p @ V
    int d = tid & 63, qp = tid >> 6;
    float acc = 0.f;
    for (int j = qp; j < NTOK; j += 4)
        acc += sm[j] * g_qkv[base + (size_t)j * QKVW + 2 * DMODEL + h * 64 + d];
    part[qp][d] = acc;
    __syncthreads();
    if (tid < 64) {
        float o = part[0][tid] + part[1][tid] + part[2][tid] + part[3][tid];
        g_ctx[(size_t)b * NTOK * DMODEL + h * 64 + tid] = o;
    }
}

// ---------------- launch ----------------
extern "C" void kernel_launch(void* const* d_in, const int* in_sizes, int n_in,
                              void* d_out, int out_size) {
    const float* x     = (const float*)d_in[0];
    const float* canny = (const float*)d_in[1];
    const float* noise = (const float*)d_in[2];
    const float* ln_w  = (const float*)d_in[3];
    const float* ln_b  = (const float*)d_in[4];
    const float* w_qkv = (const float*)d_in[5];
    const float* w_out = (const float*)d_in[6];
    const float* b_out = (const float*)d_in[7];
    float* out = (float*)d_out;

    // 1. LayerNorm
    ln_kernel<<<MTOT, 256>>>(x, ln_w, ln_b);

    // 2. QKV GEMM: [8200,768] @ [768,2304] -> g_qkv
    dim3 g_qkv_grid(QKVW / 64, (MTOT + 127) / 128);
    sgemm_kernel<0><<<g_qkv_grid, 256>>>(w_qkv, nullptr, nullptr, MTOT, QKVW, DMODEL);

    // 3. attention rows 1..1024
    dim3 g_attn(32, BATCH * NH);
    attn_kernel<<<g_attn, 256>>>();

    // 4. CLS row with prior injection
    cls_kernel<<<BATCH * NH, 256>>>(canny, noise);

    // 5. output projection: [8200,768] @ [768,768] + b_out -> d_out
    dim3 g_out(DMODEL / 64, (MTOT + 127) / 128);
    sgemm_kernel<1><<<g_out, 256>>>(w_out, b_out, out, MTOT, DMODEL, DMODEL);
}

// round 4
// speedup vs baseline: 1.1806x; 1.1806x over previous
#include <cuda_runtime.h>
#include <cuda_bf16.h>
#include <math.h>
#include <stdint.h>

#define BATCH   8
#define NTOK    1025
#define DMODEL  768
#define NH      12
#define HDIM    64
#define NPATCH  1024
#define QKVW    (3*DMODEL)          // 2304
#define EPS     1e-5f
#define LOG2E   1.4426950408889634f
#define SCALE   0.03608439182435161f   // 768^-0.5
#define MTOT    (BATCH*NTOK)        // 8200

// ---------------- scratch (device globals; no allocation) ----------------
__device__ float g_xnorm[(size_t)MTOT * DMODEL];       // 25.2 MB
__device__ float g_qkv  [(size_t)MTOT * QKVW];         // 75.6 MB
__device__ float g_ctx  [(size_t)MTOT * DMODEL];       // 25.2 MB
__device__ float g_wqkvT[(size_t)QKVW * DMODEL];       // 7.1 MB  [N,K]
__device__ float g_woutT[(size_t)DMODEL * DMODEL];     // 2.4 MB  [N,K]

// ---------------- mma.sync bf16 helper (sm_80+, no 'a' gating) ----------------
__device__ __forceinline__ void mma_bf16(float* c, const uint32_t* a, const uint32_t* b) {
    asm volatile(
        "mma.sync.aligned.m16n8k16.row.col.f32.bf16.bf16.f32 "
        "{%0,%1,%2,%3}, {%4,%5,%6,%7}, {%8,%9}, {%0,%1,%2,%3};"
        : "+f"(c[0]), "+f"(c[1]), "+f"(c[2]), "+f"(c[3])
        : "r"(a[0]), "r"(a[1]), "r"(a[2]), "r"(a[3]), "r"(b[0]), "r"(b[1]));
}

// hi/lo bf16 split of two floats -> packed bf16x2 (hi, lo)
__device__ __forceinline__ void split2(float a, float b, uint32_t& hp, uint32_t& lp) {
    __nv_bfloat16 ha = __float2bfloat16_rn(a), hb = __float2bfloat16_rn(b);
    float ra = a - __bfloat162float(ha), rb = b - __bfloat162float(hb);
    __nv_bfloat16 la = __float2bfloat16_rn(ra), lb = __float2bfloat16_rn(rb);
    hp = (uint32_t)__bfloat16_as_ushort(ha) | ((uint32_t)__bfloat16_as_ushort(hb) << 16);
    lp = (uint32_t)__bfloat16_as_ushort(la) | ((uint32_t)__bfloat16_as_ushort(lb) << 16);
}

// ---------------- weight transpose: dst[N,K] = src[K,N] ----------------
__global__ __launch_bounds__(256) void transpose_kernel(const float* __restrict__ src,
                                                        float* __restrict__ dst,
                                                        int K, int N) {
    __shared__ float t[32][33];
    int nx = blockIdx.x * 32, kx = blockIdx.y * 32;
    int lx = threadIdx.x & 31, ly = threadIdx.x >> 5;   // 32x8
    #pragma unroll
    for (int i = ly; i < 32; i += 8)
        t[i][lx] = src[(size_t)(kx + i) * N + nx + lx];
    __syncthreads();
    #pragma unroll
    for (int i = ly; i < 32; i += 8)
        dst[(size_t)(nx + i) * K + kx + lx] = t[lx][i];
}

// ================= tensor-core GEMM: C[M,N] = A[M,K] @ Bt[N,K]^T (+bias) =================
// CTA tile 128x128, BK=32, 256 threads (8 warps, 2m x 4n), warp tile 64x32.
// bf16 hi/lo 3-pass (hi*hi + lo*hi + hi*lo), fp32 accumulate.
#define SM_STRIDE 20   // uint32 units; {20*g + t} mod 32 distinct for g<8,t<4

template<int SEL>
__global__ __launch_bounds__(256) void gemm_mma(const float* __restrict__ Bt,
                                                const float* __restrict__ bias,
                                                float* __restrict__ Cext,
                                                int M, int N, int K) {
    const float* A = (SEL == 0) ? g_xnorm : g_ctx;
    float* C       = (SEL == 0) ? g_qkv   : Cext;

    // [row][k-pair] bf16x2; 16 data uint32 per row + 4 pad
    __shared__ uint32_t AsH[128][SM_STRIDE];
    __shared__ uint32_t AsL[128][SM_STRIDE];
    __shared__ uint32_t BsH[128][SM_STRIDE];
    __shared__ uint32_t BsL[128][SM_STRIDE];

    int tid = threadIdx.x;
    int wid = tid >> 5, lane = tid & 31;
    int g = lane >> 2, t = lane & 3;
    int wm = wid & 1, wn = wid >> 1;
    int m0 = blockIdx.y * 128, n0 = blockIdx.x * 128;
    int mw = wm * 64, nw = wn * 32;

    float acc[4][4][4];
    #pragma unroll
    for (int i = 0; i < 4; i++)
        #pragma unroll
        for (int j = 0; j < 4; j++)
            #pragma unroll
            for (int q = 0; q < 4; q++) acc[i][j][q] = 0.f;

    // loader mapping: 1024 float4 per tile, 4 per thread
    int r0 = tid >> 3, c4 = tid & 7;

    float4 pa[4], pb[4];
    #pragma unroll
    for (int l = 0; l < 4; l++) {
        int r = r0 + 32 * l;
        pa[l] = (m0 + r < M) ? *(const float4*)(A + (size_t)(m0 + r) * K + c4 * 4)
                             : make_float4(0.f, 0.f, 0.f, 0.f);
        pb[l] = *(const float4*)(Bt + (size_t)(n0 + r) * K + c4 * 4);
    }

    int nch = K / 32;   // 24
    for (int ch = 0; ch < nch; ch++) {
        // ---- stash prefetched chunk into smem (hi/lo split) ----
        #pragma unroll
        for (int l = 0; l < 4; l++) {
            int r = r0 + 32 * l;
            uint32_t h0, l0, h1, l1;
            split2(pa[l].x, pa[l].y, h0, l0);
            split2(pa[l].z, pa[l].w, h1, l1);
            AsH[r][c4 * 2] = h0; AsH[r][c4 * 2 + 1] = h1;
            AsL[r][c4 * 2] = l0; AsL[r][c4 * 2 + 1] = l1;
            split2(pb[l].x, pb[l].y, h0, l0);
            split2(pb[l].z, pb[l].w, h1, l1);
            BsH[r][c4 * 2] = h0; BsH[r][c4 * 2 + 1] = h1;
            BsL[r][c4 * 2] = l0; BsL[r][c4 * 2 + 1] = l1;
        }
        __syncthreads();

        // ---- prefetch next chunk (LDG issued before MMA phase) ----
        if (ch + 1 < nch) {
            int kb = (ch + 1) * 32;
            #pragma unroll
            for (int l = 0; l < 4; l++) {
                int r = r0 + 32 * l;
                pa[l] = (m0 + r < M) ? *(const float4*)(A + (size_t)(m0 + r) * K + kb + c4 * 4)
                                     : make_float4(0.f, 0.f, 0.f, 0.f);
                pb[l] = *(const float4*)(Bt + (size_t)(n0 + r) * K + kb + c4 * 4);
            }
        }

        // ---- MMA phase: 2 k16 steps x 3 passes ----
        #pragma unroll
        for (int kk = 0; kk < 2; kk++) {
            int kc = kk * 8;
            uint32_t ah[4][4], al[4][4];
            #pragma unroll
            for (int mi = 0; mi < 4; mi++) {
                int mr = mw + mi * 16 + g;
                ah[mi][0] = AsH[mr][kc + t];
                ah[mi][1] = AsH[mr + 8][kc + t];
                ah[mi][2] = AsH[mr][kc + t + 4];
                ah[mi][3] = AsH[mr + 8][kc + t + 4];
                al[mi][0] = AsL[mr][kc + t];
                al[mi][1] = AsL[mr + 8][kc + t];
                al[mi][2] = AsL[mr][kc + t + 4];
                al[mi][3] = AsL[mr + 8][kc + t + 4];
            }
            uint32_t bh[4][2], bl[4][2];
            #pragma unroll
            for (int nj = 0; nj < 4; nj++) {
                int nc = nw + nj * 8 + g;
                bh[nj][0] = BsH[nc][kc + t];
                bh[nj][1] = BsH[nc][kc + t + 4];
                bl[nj][0] = BsL[nc][kc + t];
                bl[nj][1] = BsL[nc][kc + t + 4];
            }
            #pragma unroll
            for (int mi = 0; mi < 4; mi++)
                #pragma unroll
                for (int nj = 0; nj < 4; nj++) {
                    mma_bf16(acc[mi][nj], ah[mi], bh[nj]);
                    mma_bf16(acc[mi][nj], al[mi], bh[nj]);
                    mma_bf16(acc[mi][nj], ah[mi], bl[nj]);
                }
        }
        __syncthreads();
    }

    // ---- epilogue ----
    #pragma unroll
    for (int mi = 0; mi < 4; mi++) {
        int r0e = m0 + mw + mi * 16 + g;
        #pragma unroll
        for (int nj = 0; nj < 4; nj++) {
            int col = n0 + nw + nj * 8 + t * 2;
            float b0 = 0.f, b1 = 0.f;
            if (SEL == 1) { b0 = bias[col]; b1 = bias[col + 1]; }
            if (r0e < M) {
                float2 v0 = make_float2(acc[mi][nj][0] + b0, acc[mi][nj][1] + b1);
                *(float2*)(C + (size_t)r0e * N + col) = v0;
            }
            if (r0e + 8 < M) {
                float2 v1 = make_float2(acc[mi][nj][2] + b0, acc[mi][nj][3] + b1);
                *(float2*)(C + (size_t)(r0e + 8) * N + col) = v1;
            }
        }
    }
}

// ---------------- block reduction helpers (256 threads) ----------------
__device__ __forceinline__ float blockReduceSum(float v, float* red) {
    #pragma unroll
    for (int o = 16; o > 0; o >>= 1) v += __shfl_xor_sync(0xffffffffu, v, o);
    int lane = threadIdx.x & 31, w = threadIdx.x >> 5;
    __syncthreads();
    if (lane == 0) red[w] = v;
    __syncthreads();
    if (threadIdx.x == 0) {
        float s = 0.f;
        #pragma unroll
        for (int i = 0; i < 8; i++) s += red[i];
        red[0] = s;
    }
    __syncthreads();
    return red[0];
}

__device__ __forceinline__ float blockReduceMax(float v, float* red) {
    #pragma unroll
    for (int o = 16; o > 0; o >>= 1) v = fmaxf(v, __shfl_xor_sync(0xffffffffu, v, o));
    int lane = threadIdx.x & 31, w = threadIdx.x >> 5;
    __syncthreads();
    if (lane == 0) red[w] = v;
    __syncthreads();
    if (threadIdx.x == 0) {
        float s = -1e30f;
        #pragma unroll
        for (int i = 0; i < 8; i++) s = fmaxf(s, red[i]);
        red[0] = s;
    }
    __syncthreads();
    return red[0];
}

// ---------------- LayerNorm: one row (768) per block, 256 threads ----------------
__global__ __launch_bounds__(256) void ln_kernel(const float* __restrict__ x,
                                                 const float* __restrict__ w,
                                                 const float* __restrict__ bias) {
    int row = blockIdx.x;
    const float* xr = x + (size_t)row * DMODEL;
    int t = threadIdx.x;
    float v[3];
    float s = 0.f, sq = 0.f;
    #pragma unroll
    for (int i = 0; i < 3; i++) {
        v[i] = xr[t + i * 256];
        s += v[i];
        sq += v[i] * v[i];
    }
    __shared__ float red[32];
    __shared__ float stats[2];
    #pragma unroll
    for (int o = 16; o > 0; o >>= 1) {
        s  += __shfl_xor_sync(0xffffffffu, s, o);
        sq += __shfl_xor_sync(0xffffffffu, sq, o);
    }
    int lane = t & 31, wp = t >> 5;
    if (lane == 0) { red[wp] = s; red[8 + wp] = sq; }
    __syncthreads();
    if (t == 0) {
        float a = 0.f, b2 = 0.f;
        #pragma unroll
        for (int i = 0; i < 8; i++) { a += red[i]; b2 += red[8 + i]; }
        stats[0] = a; stats[1] = b2;
    }
    __syncthreads();
    float mean = stats[0] * (1.f / DMODEL);
    float var  = stats[1] * (1.f / DMODEL) - mean * mean;
    float inv  = rsqrtf(var + EPS);
    float* o = g_xnorm + (size_t)row * DMODEL;
    #pragma unroll
    for (int i = 0; i < 3; i++) {
        int c = t + i * 256;
        o[c] = (v[i] - mean) * inv * w[c] + bias[c];
    }
}

// ---------------- Flash attention for query rows 1..1024 ----------------
__global__ __launch_bounds__(256) void attn_kernel() {
    int qt = blockIdx.x;
    int bh = blockIdx.y;
    int b = bh / NH, h = bh % NH;

    __shared__ float Qs[32][65];
    __shared__ float Ks[32][65];
    __shared__ float Vs[32][65];
    __shared__ float Ps[32][65];

    int tid = threadIdx.x;
    int row = tid >> 3, dl = tid & 7;
    size_t base = (size_t)b * NTOK * QKVW;

    #pragma unroll
    for (int l = 0; l < 2; l++) {
        int f = tid + l * 256;
        int r = f >> 4, c4 = f & 15;
        int qrow = 1 + qt * 32 + r;
        float4 v = *(const float4*)(g_qkv + base + (size_t)qrow * QKVW + h * 64 + c4 * 4);
        Qs[r][c4 * 4 + 0] = v.x;
        Qs[r][c4 * 4 + 1] = v.y;
        Qs[r][c4 * 4 + 2] = v.z;
        Qs[r][c4 * 4 + 3] = v.w;
    }

    float m = -1e30f, lsum = 0.f;
    float O[8];
    #pragma unroll
    for (int i = 0; i < 8; i++) O[i] = 0.f;

    for (int c = 0; c < 33; c++) {
        int j0 = c * 32;
        __syncthreads();
        #pragma unroll
        for (int l = 0; l < 2; l++) {
            int f = tid + l * 256;
            int r = f >> 4, c4 = f & 15;
            int j = j0 + r;
            float4 kv = make_float4(0.f, 0.f, 0.f, 0.f);
            float4 vv = make_float4(0.f, 0.f, 0.f, 0.f);
            if (j < NTOK) {
                const float* p = g_qkv + base + (size_t)j * QKVW + h * 64;
                kv = *(const float4*)(p + DMODEL     + c4 * 4);
                vv = *(const float4*)(p + 2 * DMODEL + c4 * 4);
            }
            Ks[r][c4 * 4 + 0] = kv.x; Ks[r][c4 * 4 + 1] = kv.y;
            Ks[r][c4 * 4 + 2] = kv.z; Ks[r][c4 * 4 + 3] = kv.w;
            Vs[r][c4 * 4 + 0] = vv.x; Vs[r][c4 * 4 + 1] = vv.y;
            Vs[r][c4 * 4 + 2] = vv.z; Vs[r][c4 * 4 + 3] = vv.w;
        }
        __syncthreads();

        float s[4] = {0.f, 0.f, 0.f, 0.f};
        #pragma unroll
        for (int k = 0; k < 64; k++) {
            float qv = Qs[row][k];
            #pragma unroll
            for (int i = 0; i < 4; i++) s[i] += qv * Ks[dl + 8 * i][k];
        }
        #pragma unroll
        for (int i = 0; i < 4; i++) {
            s[i] *= SCALE;
            if (j0 + dl + 8 * i >= NTOK) s[i] = -1e30f;
        }
        float cmax = fmaxf(fmaxf(s[0], s[1]), fmaxf(s[2], s[3]));
        cmax = fmaxf(cmax, __shfl_xor_sync(0xffffffffu, cmax, 1));
        cmax = fmaxf(cmax, __shfl_xor_sync(0xffffffffu, cmax, 2));
        cmax = fmaxf(cmax, __shfl_xor_sync(0xffffffffu, cmax, 4));
        float mnew = fmaxf(m, cmax);
        float fac = exp2f((m - mnew) * LOG2E);
        float p[4], psum = 0.f;
        #pragma unroll
        for (int i = 0; i < 4; i++) {
            p[i] = exp2f((s[i] - mnew) * LOG2E);
            psum += p[i];
        }
        psum += __shfl_xor_sync(0xffffffffu, psum, 1);
        psum += __shfl_xor_sync(0xffffffffu, psum, 2);
        psum += __shfl_xor_sync(0xffffffffu, psum, 4);
        lsum = lsum * fac + psum;
        m = mnew;
        #pragma unroll
        for (int i = 0; i < 8; i++) O[i] *= fac;
        #pragma unroll
        for (int i = 0; i < 4; i++) Ps[row][dl + 8 * i] = p[i];
        __syncwarp();
        #pragma unroll
        for (int j = 0; j < 32; j++) {
            float pv = Ps[row][j];
            #pragma unroll
            for (int i = 0; i < 8; i++) O[i] += pv * Vs[j][dl + 8 * i];
        }
        __syncwarp();
    }

    float invl = 1.f / lsum;
    int qrow = 1 + qt * 32 + row;
    float* o = g_ctx + ((size_t)b * NTOK + qrow) * DMODEL + h * 64;
    #pragma unroll
    for (int i = 0; i < 8; i++) o[dl + 8 * i] = O[i] * invl;
}

// ---------------- CLS row (query row 0): 96 blocks, 256 threads ----------------
__global__ __launch_bounds__(256) void cls_kernel(const float* __restrict__ canny,
                                                  const float* __restrict__ noise) {
    int bh = blockIdx.x;
    int b = bh / NH, h = bh % NH;
    __shared__ float sm[NTOK];
    __shared__ float q0[64];
    __shared__ float red[32];
    __shared__ float part[4][64];
    int tid = threadIdx.x;
    size_t base = (size_t)b * NTOK * QKVW;

    if (tid < 64) q0[tid] = g_qkv[base + h * 64 + tid];
    __syncthreads();

    for (int j = tid; j < NTOK; j += 256) {
        const float* kp = g_qkv + base + (size_t)j * QKVW + DMODEL + h * 64;
        float dot = 0.f;
        #pragma unroll
        for (int c4 = 0; c4 < 16; c4++) {
            float4 kv = *(const float4*)(kp + c4 * 4);
            dot += q0[c4 * 4 + 0] * kv.x + q0[c4 * 4 + 1] * kv.y
                 + q0[c4 * 4 + 2] * kv.z + q0[c4 * 4 + 3] * kv.w;
        }
        sm[j] = dot * SCALE;
    }
    __syncthreads();

    float mx = -1e30f, cs = 0.f, ns = 0.f;
    for (int j = tid; j < NPATCH; j += 256) {
        mx = fmaxf(mx, sm[j + 1]);
        cs += canny[(size_t)b * NPATCH + j] + 1.f;
        ns += noise[(size_t)b * NPATCH + j];
    }
    mx = blockReduceMax(mx, red);
    cs = blockReduceSum(cs, red);
    ns = blockReduceSum(ns, red);
    float se = 0.f;
    for (int j = tid; j < NPATCH; j += 256) se += exp2f((sm[j + 1] - mx) * LOG2E);
    se = blockReduceSum(se, red);
    float inv_se = 1.f / se, inv_cs = 1.f / cs, inv_ns = 1.f / ns;
    for (int j = tid; j < NPATCH; j += 256) {
        float a = exp2f((sm[j + 1] - mx) * LOG2E) * inv_se;
        sm[j + 1] = a + (canny[(size_t)b * NPATCH + j] + 1.f) * inv_cs
                      + noise[(size_t)b * NPATCH + j] * inv_ns;
    }
    __syncthreads();

    float mx2 = -1e30f;
    for (int j = tid; j < NTOK; j += 256) mx2 = fmaxf(mx2, sm[j]);
    mx2 = blockReduceMax(mx2, red);
    float se2 = 0.f;
    for (int j = tid; j < NTOK; j += 256) se2 += exp2f((sm[j] - mx2) * LOG2E);
    se2 = blockReduceSum(se2, red);
    float inv2 = 1.f / se2;
    for (int j = tid; j < NTOK; j += 256) sm[j] = exp2f((sm[j] - mx2) * LOG2E) * inv2;
    __syncthreads();

    int d = tid & 63, qp = tid >> 6;
    float acc = 0.f;
    for (int j = qp; j < NTOK; j += 4)
        acc += sm[j] * g_qkv[base + (size_t)j * QKVW + 2 * DMODEL + h * 64 + d];
    part[qp][d] = acc;
    __syncthreads();
    if (tid < 64) {
        float o = part[0][tid] + part[1][tid] + part[2][tid] + part[3][tid];
        g_ctx[(size_t)b * NTOK * DMODEL + h * 64 + tid] = o;
    }
}

// ---------------- launch ----------------
extern "C" void kernel_launch(void* const* d_in, const int* in_sizes, int n_in,
                              void* d_out, int out_size) {
    const float* x     = (const float*)d_in[0];
    const float* canny = (const float*)d_in[1];
    const float* noise = (const float*)d_in[2];
    const float* ln_w  = (const float*)d_in[3];
    const float* ln_b  = (const float*)d_in[4];
    const float* w_qkv = (const float*)d_in[5];
    const float* w_out = (const float*)d_in[6];
    const float* b_out = (const float*)d_in[7];
    float* out = (float*)d_out;

    float* wqkvT = nullptr;
    float* woutT = nullptr;
    cudaGetSymbolAddress((void**)&wqkvT, g_wqkvT);
    cudaGetSymbolAddress((void**)&woutT, g_woutT);

    // 1. LayerNorm
    ln_kernel<<<MTOT, 256>>>(x, ln_w, ln_b);

    // 1b. transpose weights to [N, K]
    {
        dim3 g1(QKVW / 32, DMODEL / 32);
        transpose_kernel<<<g1, 256>>>(w_qkv, wqkvT, DMODEL, QKVW);
        dim3 g2(DMODEL / 32, DMODEL / 32);
        transpose_kernel<<<g2, 256>>>(w_out, woutT, DMODEL, DMODEL);
    }

    // 2. QKV GEMM (mma.sync bf16 hi/lo): [8200,768] @ [768,2304] -> g_qkv
    {
        dim3 grid(QKVW / 128, (MTOT + 127) / 128);
        gemm_mma<0><<<grid, 256>>>(wqkvT, nullptr, nullptr, MTOT, QKVW, DMODEL);
    }

    // 3. attention rows 1..1024
    dim3 g_attn(32, BATCH * NH);
    attn_kernel<<<g_attn, 256>>>();

    // 4. CLS row with prior injection
    cls_kernel<<<BATCH * NH, 256>>>(canny, noise);

    // 5. output projection (mma.sync bf16 hi/lo): [8200,768] @ [768,768] + b_out -> d_out
    {
        dim3 grid(DMODEL / 128, (MTOT + 127) / 128);
        gemm_mma<1><<<grid, 256>>>(woutT, b_out, out, MTOT, DMODEL, DMODEL);
    }
}

// round 5
// speedup vs baseline: 2.8582x; 2.4209x over previous
#include <cuda_runtime.h>
#include <cuda_bf16.h>
#include <math.h>
#include <stdint.h>

#define BATCH   8
#define NTOK    1025
#define DMODEL  768
#define NH      12
#define HDIM    64
#define NPATCH  1024
#define QKVW    (3*DMODEL)          // 2304
#define EPS     1e-5f
#define LOG2E   1.4426950408889634f
#define SCALE   0.03608439182435161f   // 768^-0.5
#define MTOT    (BATCH*NTOK)        // 8200

// ---------------- scratch (device globals; no allocation) ----------------
__device__ float g_xnorm[(size_t)MTOT * DMODEL];       // 25.2 MB
__device__ float g_qkv  [(size_t)MTOT * QKVW];         // 75.6 MB
__device__ float g_ctx  [(size_t)MTOT * DMODEL];       // 25.2 MB
__device__ float g_wqkvT[(size_t)QKVW * DMODEL];       // 7.1 MB  [N,K]
__device__ float g_woutT[(size_t)DMODEL * DMODEL];     // 2.4 MB  [N,K]

// ---------------- mma.sync bf16 helper (sm_80+, no 'a' gating) ----------------
__device__ __forceinline__ void mma_bf16(float* c, const uint32_t* a, const uint32_t* b) {
    asm volatile(
        "mma.sync.aligned.m16n8k16.row.col.f32.bf16.bf16.f32 "
        "{%0,%1,%2,%3}, {%4,%5,%6,%7}, {%8,%9}, {%0,%1,%2,%3};"
        : "+f"(c[0]), "+f"(c[1]), "+f"(c[2]), "+f"(c[3])
        : "r"(a[0]), "r"(a[1]), "r"(a[2]), "r"(a[3]), "r"(b[0]), "r"(b[1]));
}

// hi/lo bf16 split of two floats -> packed bf16x2 (hi, lo)
__device__ __forceinline__ void split2(float a, float b, uint32_t& hp, uint32_t& lp) {
    __nv_bfloat16 ha = __float2bfloat16_rn(a), hb = __float2bfloat16_rn(b);
    float ra = a - __bfloat162float(ha), rb = b - __bfloat162float(hb);
    __nv_bfloat16 la = __float2bfloat16_rn(ra), lb = __float2bfloat16_rn(rb);
    hp = (uint32_t)__bfloat16_as_ushort(ha) | ((uint32_t)__bfloat16_as_ushort(hb) << 16);
    lp = (uint32_t)__bfloat16_as_ushort(la) | ((uint32_t)__bfloat16_as_ushort(lb) << 16);
}

// ---------------- weight transpose: dst[N,K] = src[K,N] ----------------
__global__ __launch_bounds__(256) void transpose_kernel(const float* __restrict__ src,
                                                        float* __restrict__ dst,
                                                        int K, int N) {
    __shared__ float t[32][33];
    int nx = blockIdx.x * 32, kx = blockIdx.y * 32;
    int lx = threadIdx.x & 31, ly = threadIdx.x >> 5;   // 32x8
    #pragma unroll
    for (int i = ly; i < 32; i += 8)
        t[i][lx] = src[(size_t)(kx + i) * N + nx + lx];
    __syncthreads();
    #pragma unroll
    for (int i = ly; i < 32; i += 8)
        dst[(size_t)(nx + i) * K + kx + lx] = t[lx][i];
}

// ================= tensor-core GEMM: C[M,N] = A[M,K] @ Bt[N,K]^T (+bias) =================
#define SM_STRIDE 20

template<int SEL>
__global__ __launch_bounds__(256) void gemm_mma(const float* __restrict__ Bt,
                                                const float* __restrict__ bias,
                                                float* __restrict__ Cext,
                                                int M, int N, int K) {
    const float* A = (SEL == 0) ? g_xnorm : g_ctx;
    float* C       = (SEL == 0) ? g_qkv   : Cext;

    __shared__ uint32_t AsH[128][SM_STRIDE];
    __shared__ uint32_t AsL[128][SM_STRIDE];
    __shared__ uint32_t BsH[128][SM_STRIDE];
    __shared__ uint32_t BsL[128][SM_STRIDE];

    int tid = threadIdx.x;
    int wid = tid >> 5, lane = tid & 31;
    int g = lane >> 2, t = lane & 3;
    int wm = wid & 1, wn = wid >> 1;
    int m0 = blockIdx.y * 128, n0 = blockIdx.x * 128;
    int mw = wm * 64, nw = wn * 32;

    float acc[4][4][4];
    #pragma unroll
    for (int i = 0; i < 4; i++)
        #pragma unroll
        for (int j = 0; j < 4; j++)
            #pragma unroll
            for (int q = 0; q < 4; q++) acc[i][j][q] = 0.f;

    int r0 = tid >> 3, c4 = tid & 7;

    float4 pa[4], pb[4];
    #pragma unroll
    for (int l = 0; l < 4; l++) {
        int r = r0 + 32 * l;
        pa[l] = (m0 + r < M) ? *(const float4*)(A + (size_t)(m0 + r) * K + c4 * 4)
                             : make_float4(0.f, 0.f, 0.f, 0.f);
        pb[l] = *(const float4*)(Bt + (size_t)(n0 + r) * K + c4 * 4);
    }

    int nch = K / 32;
    for (int ch = 0; ch < nch; ch++) {
        #pragma unroll
        for (int l = 0; l < 4; l++) {
            int r = r0 + 32 * l;
            uint32_t h0, l0, h1, l1;
            split2(pa[l].x, pa[l].y, h0, l0);
            split2(pa[l].z, pa[l].w, h1, l1);
            AsH[r][c4 * 2] = h0; AsH[r][c4 * 2 + 1] = h1;
            AsL[r][c4 * 2] = l0; AsL[r][c4 * 2 + 1] = l1;
            split2(pb[l].x, pb[l].y, h0, l0);
            split2(pb[l].z, pb[l].w, h1, l1);
            BsH[r][c4 * 2] = h0; BsH[r][c4 * 2 + 1] = h1;
            BsL[r][c4 * 2] = l0; BsL[r][c4 * 2 + 1] = l1;
        }
        __syncthreads();

        if (ch + 1 < nch) {
            int kb = (ch + 1) * 32;
            #pragma unroll
            for (int l = 0; l < 4; l++) {
                int r = r0 + 32 * l;
                pa[l] = (m0 + r < M) ? *(const float4*)(A + (size_t)(m0 + r) * K + kb + c4 * 4)
                                     : make_float4(0.f, 0.f, 0.f, 0.f);
                pb[l] = *(const float4*)(Bt + (size_t)(n0 + r) * K + kb + c4 * 4);
            }
        }

        #pragma unroll
        for (int kk = 0; kk < 2; kk++) {
            int kc = kk * 8;
            uint32_t ah[4][4], al[4][4];
            #pragma unroll
            for (int mi = 0; mi < 4; mi++) {
                int mr = mw + mi * 16 + g;
                ah[mi][0] = AsH[mr][kc + t];
                ah[mi][1] = AsH[mr + 8][kc + t];
                ah[mi][2] = AsH[mr][kc + t + 4];
                ah[mi][3] = AsH[mr + 8][kc + t + 4];
                al[mi][0] = AsL[mr][kc + t];
                al[mi][1] = AsL[mr + 8][kc + t];
                al[mi][2] = AsL[mr][kc + t + 4];
                al[mi][3] = AsL[mr + 8][kc + t + 4];
            }
            uint32_t bh[4][2], bl[4][2];
            #pragma unroll
            for (int nj = 0; nj < 4; nj++) {
                int nc = nw + nj * 8 + g;
                bh[nj][0] = BsH[nc][kc + t];
                bh[nj][1] = BsH[nc][kc + t + 4];
                bl[nj][0] = BsL[nc][kc + t];
                bl[nj][1] = BsL[nc][kc + t + 4];
            }
            #pragma unroll
            for (int mi = 0; mi < 4; mi++)
                #pragma unroll
                for (int nj = 0; nj < 4; nj++) {
                    mma_bf16(acc[mi][nj], ah[mi], bh[nj]);
                    mma_bf16(acc[mi][nj], al[mi], bh[nj]);
                    mma_bf16(acc[mi][nj], ah[mi], bl[nj]);
                }
        }
        __syncthreads();
    }

    #pragma unroll
    for (int mi = 0; mi < 4; mi++) {
        int r0e = m0 + mw + mi * 16 + g;
        #pragma unroll
        for (int nj = 0; nj < 4; nj++) {
            int col = n0 + nw + nj * 8 + t * 2;
            float b0 = 0.f, b1 = 0.f;
            if (SEL == 1) { b0 = bias[col]; b1 = bias[col + 1]; }
            if (r0e < M) {
                float2 v0 = make_float2(acc[mi][nj][0] + b0, acc[mi][nj][1] + b1);
                *(float2*)(C + (size_t)r0e * N + col) = v0;
            }
            if (r0e + 8 < M) {
                float2 v1 = make_float2(acc[mi][nj][2] + b0, acc[mi][nj][3] + b1);
                *(float2*)(C + (size_t)(r0e + 8) * N + col) = v1;
            }
        }
    }
}

// ================= tensor-core flash attention (rows 1..1024) =================
// grid (16 qtiles, 96 bh), 128 threads (4 warps x m16). 64-key chunks, 17 chunks.
// QK^T and PV both bf16 hi/lo 3-pass on mma.sync.
__global__ __launch_bounds__(128) void attn_mma_kernel() {
    int qt = blockIdx.x;
    int bh_ = blockIdx.y;
    int b = bh_ / NH, h = bh_ % NH;

    __shared__ uint32_t KsH[64][36];   // [key][dim-pair] bf16x2 hi
    __shared__ uint32_t KsL[64][36];   // lo
    __shared__ float    Vs[64][68];    // [key][dim] fp32

    int tid = threadIdx.x, wid = tid >> 5, lane = tid & 31;
    int g = lane >> 2, t = lane & 3;
    size_t base = (size_t)b * NTOK * QKVW;

    // ---- Q fragments: rows row0+g, row0+g+8; pre-scaled by SCALE*LOG2E ----
    int row0 = 1 + qt * 64 + wid * 16;
    const float qsc = SCALE * LOG2E;
    const float* Qp0 = g_qkv + base + (size_t)(row0 + g) * QKVW + h * 64;
    const float* Qp1 = g_qkv + base + (size_t)(row0 + g + 8) * QKVW + h * 64;
    uint32_t qh[4][4], ql[4][4];
    #pragma unroll
    for (int kk = 0; kk < 4; kk++) {
        int k0 = kk * 16 + 2 * t;
        float2 a0 = *(const float2*)(Qp0 + k0);
        float2 a1 = *(const float2*)(Qp1 + k0);
        float2 a2 = *(const float2*)(Qp0 + k0 + 8);
        float2 a3 = *(const float2*)(Qp1 + k0 + 8);
        split2(a0.x * qsc, a0.y * qsc, qh[kk][0], ql[kk][0]);
        split2(a1.x * qsc, a1.y * qsc, qh[kk][1], ql[kk][1]);
        split2(a2.x * qsc, a2.y * qsc, qh[kk][2], ql[kk][2]);
        split2(a3.x * qsc, a3.y * qsc, qh[kk][3], ql[kk][3]);
    }

    float O[8][4];
    #pragma unroll
    for (int nj = 0; nj < 8; nj++)
        #pragma unroll
        for (int q = 0; q < 4; q++) O[nj][q] = 0.f;
    float mr0 = -1e30f, mr1 = -1e30f, lr0 = 0.f, lr1 = 0.f;

    for (int c = 0; c < 17; c++) {
        int j0 = c * 64;
        __syncthreads();
        // ---- load K (bf16 hi/lo) + V (fp32) chunk: 64 rows x 64 dims ----
        #pragma unroll
        for (int l = 0; l < 8; l++) {
            int idx = tid + l * 128;
            int r = idx >> 4, c4 = idx & 15;
            int j = j0 + r;
            float4 kv = make_float4(0.f, 0.f, 0.f, 0.f);
            float4 vv = make_float4(0.f, 0.f, 0.f, 0.f);
            if (j < NTOK) {
                const float* p = g_qkv + base + (size_t)j * QKVW + h * 64;
                kv = *(const float4*)(p + DMODEL     + c4 * 4);
                vv = *(const float4*)(p + 2 * DMODEL + c4 * 4);
            }
            uint32_t h0, l0_, h1, l1_;
            split2(kv.x, kv.y, h0, l0_);
            split2(kv.z, kv.w, h1, l1_);
            KsH[r][c4 * 2] = h0; KsH[r][c4 * 2 + 1] = h1;
            KsL[r][c4 * 2] = l0_; KsL[r][c4 * 2 + 1] = l1_;
            *(float4*)&Vs[r][c4 * 4] = vv;
        }
        __syncthreads();

        // ---- S = Q K^T (scaled, log2 domain) ----
        float S[8][4];
        #pragma unroll
        for (int nj = 0; nj < 8; nj++)
            #pragma unroll
            for (int q = 0; q < 4; q++) S[nj][q] = 0.f;

        #pragma unroll
        for (int kk = 0; kk < 4; kk++) {
            int kc = kk * 8;
            #pragma unroll
            for (int nj = 0; nj < 8; nj++) {
                int nc = 8 * nj + g;
                uint32_t kb[2], kl[2];
                kb[0] = KsH[nc][kc + t]; kb[1] = KsH[nc][kc + t + 4];
                kl[0] = KsL[nc][kc + t]; kl[1] = KsL[nc][kc + t + 4];
                mma_bf16(S[nj], qh[kk], kb);
                mma_bf16(S[nj], ql[kk], kb);
                mma_bf16(S[nj], qh[kk], kl);
            }
        }

        // ---- mask invalid keys (only last chunk) ----
        if (j0 + 64 > NTOK) {
            #pragma unroll
            for (int nj = 0; nj < 8; nj++) {
                int col = j0 + 8 * nj + 2 * t;
                if (col >= NTOK)     { S[nj][0] = -1e30f; S[nj][2] = -1e30f; }
                if (col + 1 >= NTOK) { S[nj][1] = -1e30f; S[nj][3] = -1e30f; }
            }
        }

        // ---- online softmax (log2 domain) ----
        float cm0 = -1e30f, cm1 = -1e30f;
        #pragma unroll
        for (int nj = 0; nj < 8; nj++) {
            cm0 = fmaxf(cm0, fmaxf(S[nj][0], S[nj][1]));
            cm1 = fmaxf(cm1, fmaxf(S[nj][2], S[nj][3]));
        }
        cm0 = fmaxf(cm0, __shfl_xor_sync(0xffffffffu, cm0, 1));
        cm0 = fmaxf(cm0, __shfl_xor_sync(0xffffffffu, cm0, 2));
        cm1 = fmaxf(cm1, __shfl_xor_sync(0xffffffffu, cm1, 1));
        cm1 = fmaxf(cm1, __shfl_xor_sync(0xffffffffu, cm1, 2));
        float mn0 = fmaxf(mr0, cm0), mn1 = fmaxf(mr1, cm1);
        float f0 = exp2f(mr0 - mn0), f1 = exp2f(mr1 - mn1);
        float ps0 = 0.f, ps1 = 0.f;
        #pragma unroll
        for (int nj = 0; nj < 8; nj++) {
            S[nj][0] = exp2f(S[nj][0] - mn0);
            S[nj][1] = exp2f(S[nj][1] - mn0);
            S[nj][2] = exp2f(S[nj][2] - mn1);
            S[nj][3] = exp2f(S[nj][3] - mn1);
            ps0 += S[nj][0] + S[nj][1];
            ps1 += S[nj][2] + S[nj][3];
        }
        ps0 += __shfl_xor_sync(0xffffffffu, ps0, 1);
        ps0 += __shfl_xor_sync(0xffffffffu, ps0, 2);
        ps1 += __shfl_xor_sync(0xffffffffu, ps1, 1);
        ps1 += __shfl_xor_sync(0xffffffffu, ps1, 2);
        lr0 = lr0 * f0 + ps0;
        lr1 = lr1 * f1 + ps1;
        mr0 = mn0; mr1 = mn1;
        #pragma unroll
        for (int nj = 0; nj < 8; nj++) {
            O[nj][0] *= f0; O[nj][1] *= f0;
            O[nj][2] *= f1; O[nj][3] *= f1;
        }

        // ---- O += P @ V (hi/lo 3-pass; V frags read fp32 from smem) ----
        #pragma unroll
        for (int kk = 0; kk < 4; kk++) {
            int j2 = 2 * kk;
            uint32_t ph[4], pl[4];
            split2(S[j2][0],     S[j2][1],     ph[0], pl[0]);
            split2(S[j2][2],     S[j2][3],     ph[1], pl[1]);
            split2(S[j2 + 1][0], S[j2 + 1][1], ph[2], pl[2]);
            split2(S[j2 + 1][2], S[j2 + 1][3], ph[3], pl[3]);
            int k0 = 16 * kk + 2 * t;
            #pragma unroll
            for (int nj = 0; nj < 8; nj++) {
                int n = 8 * nj + g;
                uint32_t vh[2], vl[2];
                split2(Vs[k0][n],     Vs[k0 + 1][n], vh[0], vl[0]);
                split2(Vs[k0 + 8][n], Vs[k0 + 9][n], vh[1], vl[1]);
                mma_bf16(O[nj], ph, vh);
                mma_bf16(O[nj], pl, vh);
                mma_bf16(O[nj], ph, vl);
            }
        }
    }

    // ---- write out ----
    float i0 = 1.f / lr0, i1 = 1.f / lr1;
    float* o0 = g_ctx + ((size_t)b * NTOK + row0 + g) * DMODEL + h * 64;
    float* o1 = g_ctx + ((size_t)b * NTOK + row0 + g + 8) * DMODEL + h * 64;
    #pragma unroll
    for (int nj = 0; nj < 8; nj++) {
        int col = 8 * nj + 2 * t;
        *(float2*)(o0 + col) = make_float2(O[nj][0] * i0, O[nj][1] * i0);
        *(float2*)(o1 + col) = make_float2(O[nj][2] * i1, O[nj][3] * i1);
    }
}

// ---------------- block reduction helpers (256 threads) ----------------
__device__ __forceinline__ float blockReduceSum(float v, float* red) {
    #pragma unroll
    for (int o = 16; o > 0; o >>= 1) v += __shfl_xor_sync(0xffffffffu, v, o);
    int lane = threadIdx.x & 31, w = threadIdx.x >> 5;
    __syncthreads();
    if (lane == 0) red[w] = v;
    __syncthreads();
    if (threadIdx.x == 0) {
        float s = 0.f;
        #pragma unroll
        for (int i = 0; i < 8; i++) s += red[i];
        red[0] = s;
    }
    __syncthreads();
    return red[0];
}

__device__ __forceinline__ float blockReduceMax(float v, float* red) {
    #pragma unroll
    for (int o = 16; o > 0; o >>= 1) v = fmaxf(v, __shfl_xor_sync(0xffffffffu, v, o));
    int lane = threadIdx.x & 31, w = threadIdx.x >> 5;
    __syncthreads();
    if (lane == 0) red[w] = v;
    __syncthreads();
    if (threadIdx.x == 0) {
        float s = -1e30f;
        #pragma unroll
        for (int i = 0; i < 8; i++) s = fmaxf(s, red[i]);
        red[0] = s;
    }
    __syncthreads();
    return red[0];
}

// ---------------- LayerNorm: one row (768) per block, 256 threads ----------------
__global__ __launch_bounds__(256) void ln_kernel(const float* __restrict__ x,
                                                 const float* __restrict__ w,
                                                 const float* __restrict__ bias) {
    int row = blockIdx.x;
    const float* xr = x + (size_t)row * DMODEL;
    int t = threadIdx.x;
    float v[3];
    float s = 0.f, sq = 0.f;
    #pragma unroll
    for (int i = 0; i < 3; i++) {
        v[i] = xr[t + i * 256];
        s += v[i];
        sq += v[i] * v[i];
    }
    __shared__ float red[32];
    __shared__ float stats[2];
    #pragma unroll
    for (int o = 16; o > 0; o >>= 1) {
        s  += __shfl_xor_sync(0xffffffffu, s, o);
        sq += __shfl_xor_sync(0xffffffffu, sq, o);
    }
    int lane = t & 31, wp = t >> 5;
    if (lane == 0) { red[wp] = s; red[8 + wp] = sq; }
    __syncthreads();
    if (t == 0) {
        float a = 0.f, b2 = 0.f;
        #pragma unroll
        for (int i = 0; i < 8; i++) { a += red[i]; b2 += red[8 + i]; }
        stats[0] = a; stats[1] = b2;
    }
    __syncthreads();
    float mean = stats[0] * (1.f / DMODEL);
    float var  = stats[1] * (1.f / DMODEL) - mean * mean;
    float inv  = rsqrtf(var + EPS);
    float* o = g_xnorm + (size_t)row * DMODEL;
    #pragma unroll
    for (int i = 0; i < 3; i++) {
        int c = t + i * 256;
        o[c] = (v[i] - mean) * inv * w[c] + bias[c];
    }
}

// ---------------- CLS row (query row 0): 96 blocks, 256 threads ----------------
__global__ __launch_bounds__(256) void cls_kernel(const float* __restrict__ canny,
                                                  const float* __restrict__ noise) {
    int bh = blockIdx.x;
    int b = bh / NH, h = bh % NH;
    __shared__ float sm[NTOK];
    __shared__ float q0[64];
    __shared__ float red[32];
    __shared__ float part[4][64];
    int tid = threadIdx.x;
    size_t base = (size_t)b * NTOK * QKVW;

    if (tid < 64) q0[tid] = g_qkv[base + h * 64 + tid];
    __syncthreads();

    for (int j = tid; j < NTOK; j += 256) {
        const float* kp = g_qkv + base + (size_t)j * QKVW + DMODEL + h * 64;
        float dot = 0.f;
        #pragma unroll
        for (int c4 = 0; c4 < 16; c4++) {
            float4 kv = *(const float4*)(kp + c4 * 4);
            dot += q0[c4 * 4 + 0] * kv.x + q0[c4 * 4 + 1] * kv.y
                 + q0[c4 * 4 + 2] * kv.z + q0[c4 * 4 + 3] * kv.w;
        }
        sm[j] = dot * SCALE;
    }
    __syncthreads();

    float mx = -1e30f, cs = 0.f, ns = 0.f;
    for (int j = tid; j < NPATCH; j += 256) {
        mx = fmaxf(mx, sm[j + 1]);
        cs += canny[(size_t)b * NPATCH + j] + 1.f;
        ns += noise[(size_t)b * NPATCH + j];
    }
    mx = blockReduceMax(mx, red);
    cs = blockReduceSum(cs, red);
    ns = blockReduceSum(ns, red);
    float se = 0.f;
    for (int j = tid; j < NPATCH; j += 256) se += exp2f((sm[j + 1] - mx) * LOG2E);
    se = blockReduceSum(se, red);
    float inv_se = 1.f / se, inv_cs = 1.f / cs, inv_ns = 1.f / ns;
    for (int j = tid; j < NPATCH; j += 256) {
        float a = exp2f((sm[j + 1] - mx) * LOG2E) * inv_se;
        sm[j + 1] = a + (canny[(size_t)b * NPATCH + j] + 1.f) * inv_cs
                      + noise[(size_t)b * NPATCH + j] * inv_ns;
    }
    __syncthreads();

    float mx2 = -1e30f;
    for (int j = tid; j < NTOK; j += 256) mx2 = fmaxf(mx2, sm[j]);
    mx2 = blockReduceMax(mx2, red);
    float se2 = 0.f;
    for (int j = tid; j < NTOK; j += 256) se2 += exp2f((sm[j] - mx2) * LOG2E);
    se2 = blockReduceSum(se2, red);
    float inv2 = 1.f / se2;
    for (int j = tid; j < NTOK; j += 256) sm[j] = exp2f((sm[j] - mx2) * LOG2E) * inv2;
    __syncthreads();

    int d = tid & 63, qp = tid >> 6;
    float acc = 0.f;
    for (int j = qp; j < NTOK; j += 4)
        acc += sm[j] * g_qkv[base + (size_t)j * QKVW + 2 * DMODEL + h * 64 + d];
    part[qp][d] = acc;
    __syncthreads();
    if (tid < 64) {
        float o = part[0][tid] + part[1][tid] + part[2][tid] + part[3][tid];
        g_ctx[(size_t)b * NTOK * DMODEL + h * 64 + tid] = o;
    }
}

// ---------------- launch ----------------
extern "C" void kernel_launch(void* const* d_in, const int* in_sizes, int n_in,
                              void* d_out, int out_size) {
    const float* x     = (const float*)d_in[0];
    const float* canny = (const float*)d_in[1];
    const float* noise = (const float*)d_in[2];
    const float* ln_w  = (const float*)d_in[3];
    const float* ln_b  = (const float*)d_in[4];
    const float* w_qkv = (const float*)d_in[5];
    const float* w_out = (const float*)d_in[6];
    const float* b_out = (const float*)d_in[7];
    float* out = (float*)d_out;

    float* wqkvT = nullptr;
    float* woutT = nullptr;
    cudaGetSymbolAddress((void**)&wqkvT, g_wqkvT);
    cudaGetSymbolAddress((void**)&woutT, g_woutT);

    // 1. LayerNorm
    ln_kernel<<<MTOT, 256>>>(x, ln_w, ln_b);

    // 1b. transpose weights to [N, K]
    {
        dim3 g1(QKVW / 32, DMODEL / 32);
        transpose_kernel<<<g1, 256>>>(w_qkv, wqkvT, DMODEL, QKVW);
        dim3 g2(DMODEL / 32, DMODEL / 32);
        transpose_kernel<<<g2, 256>>>(w_out, woutT, DMODEL, DMODEL);
    }

    // 2. QKV GEMM (mma.sync bf16 hi/lo): [8200,768] @ [768,2304] -> g_qkv
    {
        dim3 grid(QKVW / 128, (MTOT + 127) / 128);
        gemm_mma<0><<<grid, 256>>>(wqkvT, nullptr, nullptr, MTOT, QKVW, DMODEL);
    }

    // 3. attention rows 1..1024 (tensor-core flash)
    {
        dim3 g_attn(16, BATCH * NH);
        attn_mma_kernel<<<g_attn, 128>>>();
    }

    // 4. CLS row with prior injection
    cls_kernel<<<BATCH * NH, 256>>>(canny, noise);

    // 5. output projection (mma.sync bf16 hi/lo): [8200,768] @ [768,768] + b_out -> d_out
    {
        dim3 grid(DMODEL / 128, (MTOT + 127) / 128);
        gemm_mma<1><<<grid, 256>>>(woutT, b_out, out, MTOT, DMODEL, DMODEL);
    }
}

// round 6
// speedup vs baseline: 3.0637x; 1.0719x over previous
#include <cuda_runtime.h>
#include <cuda_bf16.h>
#include <math.h>
#include <stdint.h>

#define BATCH   8
#define NTOK    1025
#define DMODEL  768
#define NH      12
#define HDIM    64
#define NPATCH  1024
#define QKVW    (3*DMODEL)          // 2304
#define EPS     1e-5f
#define LOG2E   1.4426950408889634f
#define SCALE   0.03608439182435161f   // 768^-0.5
#define MTOT    (BATCH*NTOK)        // 8200

// ---------------- scratch (device globals; no allocation) ----------------
__device__ float g_xnorm[(size_t)MTOT * DMODEL];
__device__ float g_qkv  [(size_t)MTOT * QKVW];
__device__ float g_ctx  [(size_t)MTOT * DMODEL];
__device__ float g_wqkvT[(size_t)QKVW * DMODEL];
__device__ float g_woutT[(size_t)DMODEL * DMODEL];

// ---------------- helpers ----------------
__device__ __forceinline__ uint32_t smem_u32(const void* p) {
    uint32_t a;
    asm("{ .reg .u64 t; cvta.to.shared.u64 t, %1; cvt.u32.u64 %0, t; }" : "=r"(a) : "l"(p));
    return a;
}

__device__ __forceinline__ void mma_bf16(float* c, const uint32_t* a, const uint32_t* b) {
    asm volatile(
        "mma.sync.aligned.m16n8k16.row.col.f32.bf16.bf16.f32 "
        "{%0,%1,%2,%3}, {%4,%5,%6,%7}, {%8,%9}, {%0,%1,%2,%3};"
        : "+f"(c[0]), "+f"(c[1]), "+f"(c[2]), "+f"(c[3])
        : "r"(a[0]), "r"(a[1]), "r"(a[2]), "r"(a[3]), "r"(b[0]), "r"(b[1]));
}

__device__ __forceinline__ void ldsm_x4(uint32_t* f, uint32_t addr) {
    asm volatile("ldmatrix.sync.aligned.m8n8.x4.shared.b16 {%0,%1,%2,%3}, [%4];"
        : "=r"(f[0]), "=r"(f[1]), "=r"(f[2]), "=r"(f[3]) : "r"(addr));
}
__device__ __forceinline__ void ldsm_x2(uint32_t* f, uint32_t addr) {
    asm volatile("ldmatrix.sync.aligned.m8n8.x2.shared.b16 {%0,%1}, [%2];"
        : "=r"(f[0]), "=r"(f[1]) : "r"(addr));
}

// hi/lo bf16 split of two floats -> packed bf16x2 (hi, lo); a in low half
__device__ __forceinline__ void split2(float a, float b, uint32_t& hp, uint32_t& lp) {
    __nv_bfloat16 ha = __float2bfloat16_rn(a), hb = __float2bfloat16_rn(b);
    float ra = a - __bfloat162float(ha), rb = b - __bfloat162float(hb);
    __nv_bfloat16 la = __float2bfloat16_rn(ra), lb = __float2bfloat16_rn(rb);
    hp = (uint32_t)__bfloat16_as_ushort(ha) | ((uint32_t)__bfloat16_as_ushort(hb) << 16);
    lp = (uint32_t)__bfloat16_as_ushort(la) | ((uint32_t)__bfloat16_as_ushort(lb) << 16);
}

// ---------------- weight transpose: dst[N,K] = src[K,N] ----------------
__global__ __launch_bounds__(256) void transpose_kernel(const float* __restrict__ src,
                                                        float* __restrict__ dst,
                                                        int K, int N) {
    __shared__ float t[32][33];
    int nx = blockIdx.x * 32, kx = blockIdx.y * 32;
    int lx = threadIdx.x & 31, ly = threadIdx.x >> 5;
    #pragma unroll
    for (int i = ly; i < 32; i += 8)
        t[i][lx] = src[(size_t)(kx + i) * N + nx + lx];
    __syncthreads();
    #pragma unroll
    for (int i = ly; i < 32; i += 8)
        dst[(size_t)(nx + i) * K + kx + lx] = t[lx][i];
}

// ================= tensor-core GEMM: C[M,N] = A[M,K] @ Bt[N,K]^T (+bias) =================
#define SM_STRIDE 20

template<int SEL>
__global__ __launch_bounds__(256) void gemm_mma(const float* __restrict__ Bt,
                                                const float* __restrict__ bias,
                                                float* __restrict__ Cext,
                                                int M, int N, int K) {
    const float* A = (SEL == 0) ? g_xnorm : g_ctx;
    float* C       = (SEL == 0) ? g_qkv   : Cext;

    __shared__ uint32_t AsH[128][SM_STRIDE];
    __shared__ uint32_t AsL[128][SM_STRIDE];
    __shared__ uint32_t BsH[128][SM_STRIDE];
    __shared__ uint32_t BsL[128][SM_STRIDE];

    int tid = threadIdx.x;
    int wid = tid >> 5, lane = tid & 31;
    int g = lane >> 2, t = lane & 3;
    int wm = wid & 1, wn = wid >> 1;
    int m0 = blockIdx.y * 128, n0 = blockIdx.x * 128;
    int mw = wm * 64, nw = wn * 32;

    // per-lane ldmatrix byte offsets
    int rA = (lane & 7) + ((lane >> 3) & 1) * 8;
    int cA = (lane >> 4) * 4;
    uint32_t aoff = (uint32_t)(rA * SM_STRIDE + cA) * 4u;
    int rB = lane & 7;
    int cB = ((lane >> 3) & 1) * 4;
    uint32_t boff = (uint32_t)(rB * SM_STRIDE + cB) * 4u;

    uint32_t uAsH = smem_u32(&AsH[0][0]);
    uint32_t uAsL = smem_u32(&AsL[0][0]);
    uint32_t uBsH = smem_u32(&BsH[0][0]);
    uint32_t uBsL = smem_u32(&BsL[0][0]);

    float acc[4][4][4];
    #pragma unroll
    for (int i = 0; i < 4; i++)
        #pragma unroll
        for (int j = 0; j < 4; j++)
            #pragma unroll
            for (int q = 0; q < 4; q++) acc[i][j][q] = 0.f;

    int r0 = tid >> 3, c4 = tid & 7;

    float4 pa[4], pb[4];
    #pragma unroll
    for (int l = 0; l < 4; l++) {
        int r = r0 + 32 * l;
        pa[l] = (m0 + r < M) ? *(const float4*)(A + (size_t)(m0 + r) * K + c4 * 4)
                             : make_float4(0.f, 0.f, 0.f, 0.f);
        pb[l] = *(const float4*)(Bt + (size_t)(n0 + r) * K + c4 * 4);
    }

    int nch = K / 32;
    for (int ch = 0; ch < nch; ch++) {
        #pragma unroll
        for (int l = 0; l < 4; l++) {
            int r = r0 + 32 * l;
            uint32_t h0, l0, h1, l1;
            split2(pa[l].x, pa[l].y, h0, l0);
            split2(pa[l].z, pa[l].w, h1, l1);
            AsH[r][c4 * 2] = h0; AsH[r][c4 * 2 + 1] = h1;
            AsL[r][c4 * 2] = l0; AsL[r][c4 * 2 + 1] = l1;
            split2(pb[l].x, pb[l].y, h0, l0);
            split2(pb[l].z, pb[l].w, h1, l1);
            BsH[r][c4 * 2] = h0; BsH[r][c4 * 2 + 1] = h1;
            BsL[r][c4 * 2] = l0; BsL[r][c4 * 2 + 1] = l1;
        }
        __syncthreads();

        if (ch + 1 < nch) {
            int kb = (ch + 1) * 32;
            #pragma unroll
            for (int l = 0; l < 4; l++) {
                int r = r0 + 32 * l;
                pa[l] = (m0 + r < M) ? *(const float4*)(A + (size_t)(m0 + r) * K + kb + c4 * 4)
                                     : make_float4(0.f, 0.f, 0.f, 0.f);
                pb[l] = *(const float4*)(Bt + (size_t)(n0 + r) * K + kb + c4 * 4);
            }
        }

        #pragma unroll
        for (int kk = 0; kk < 2; kk++) {
            uint32_t kcb = (uint32_t)(kk * 8) * 4u;
            uint32_t ah[4][4], al[4][4];
            #pragma unroll
            for (int mi = 0; mi < 4; mi++) {
                uint32_t base = (uint32_t)((mw + mi * 16) * SM_STRIDE) * 4u + kcb + aoff;
                ldsm_x4(ah[mi], uAsH + base);
                ldsm_x4(al[mi], uAsL + base);
            }
            uint32_t bh[4][2], bl[4][2];
            #pragma unroll
            for (int nj = 0; nj < 4; nj++) {
                uint32_t base = (uint32_t)((nw + nj * 8) * SM_STRIDE) * 4u + kcb + boff;
                ldsm_x2(bh[nj], uBsH + base);
                ldsm_x2(bl[nj], uBsL + base);
            }
            #pragma unroll
            for (int mi = 0; mi < 4; mi++)
                #pragma unroll
                for (int nj = 0; nj < 4; nj++) {
                    mma_bf16(acc[mi][nj], ah[mi], bh[nj]);
                    mma_bf16(acc[mi][nj], al[mi], bh[nj]);
                    mma_bf16(acc[mi][nj], ah[mi], bl[nj]);
                }
        }
        __syncthreads();
    }

    #pragma unroll
    for (int mi = 0; mi < 4; mi++) {
        int r0e = m0 + mw + mi * 16 + g;
        #pragma unroll
        for (int nj = 0; nj < 4; nj++) {
            int col = n0 + nw + nj * 8 + t * 2;
            float b0 = 0.f, b1 = 0.f;
            if (SEL == 1) { b0 = bias[col]; b1 = bias[col + 1]; }
            if (r0e < M) {
                float2 v0 = make_float2(acc[mi][nj][0] + b0, acc[mi][nj][1] + b1);
                *(float2*)(C + (size_t)r0e * N + col) = v0;
            }
            if (r0e + 8 < M) {
                float2 v1 = make_float2(acc[mi][nj][2] + b0, acc[mi][nj][3] + b1);
                *(float2*)(C + (size_t)(r0e + 8) * N + col) = v1;
            }
        }
    }
}

// ================= tensor-core flash attention (rows 1..1024) =================
// grid (8 qtiles, 96 bh), 256 threads (8 warps x m16 = 128 q rows / block).
// K and V both pre-split to bf16 hi/lo in smem; V stored [dim][key-pair]
// (= B-fragment layout) so PV needs no per-warp splits.
__global__ __launch_bounds__(256) void attn_mma_kernel() {
    int qt = blockIdx.x;
    int bh_ = blockIdx.y;
    int b = bh_ / NH, h = bh_ % NH;

    __shared__ uint32_t KsH[64][36];   // [key][dim-pair]
    __shared__ uint32_t KsL[64][36];
    __shared__ uint32_t VsH[64][36];   // [dim][key-pair]
    __shared__ uint32_t VsL[64][36];

    int tid = threadIdx.x, wid = tid >> 5, lane = tid & 31;
    int g = lane >> 2, t = lane & 3;
    size_t base = (size_t)b * NTOK * QKVW;

    // ---- Q fragments: rows row0+g, row0+g+8; pre-scaled by SCALE*LOG2E ----
    int row0 = 1 + qt * 128 + wid * 16;
    const float qsc = SCALE * LOG2E;
    const float* Qp0 = g_qkv + base + (size_t)(row0 + g) * QKVW + h * 64;
    const float* Qp1 = g_qkv + base + (size_t)(row0 + g + 8) * QKVW + h * 64;
    uint32_t qh[4][4], ql[4][4];
    #pragma unroll
    for (int kk = 0; kk < 4; kk++) {
        int k0 = kk * 16 + 2 * t;
        float2 a0 = *(const float2*)(Qp0 + k0);
        float2 a1 = *(const float2*)(Qp1 + k0);
        float2 a2 = *(const float2*)(Qp0 + k0 + 8);
        float2 a3 = *(const float2*)(Qp1 + k0 + 8);
        split2(a0.x * qsc, a0.y * qsc, qh[kk][0], ql[kk][0]);
        split2(a1.x * qsc, a1.y * qsc, qh[kk][1], ql[kk][1]);
        split2(a2.x * qsc, a2.y * qsc, qh[kk][2], ql[kk][2]);
        split2(a3.x * qsc, a3.y * qsc, qh[kk][3], ql[kk][3]);
    }

    float O[8][4];
    #pragma unroll
    for (int nj = 0; nj < 8; nj++)
        #pragma unroll
        for (int q = 0; q < 4; q++) O[nj][q] = 0.f;
    float mr0 = -1e30f, mr1 = -1e30f, lr0 = 0.f, lr1 = 0.f;

    for (int c = 0; c < 17; c++) {
        int j0 = c * 64;
        __syncthreads();
        // ---- K chunk: 64 keys x 64 dims, hi/lo split, [key][dim-pair] ----
        #pragma unroll
        for (int l = 0; l < 4; l++) {
            int idx = tid + l * 256;
            int r = idx >> 4, c4 = idx & 15;
            int j = j0 + r;
            float4 kv = make_float4(0.f, 0.f, 0.f, 0.f);
            if (j < NTOK)
                kv = *(const float4*)(g_qkv + base + (size_t)j * QKVW + DMODEL + h * 64 + c4 * 4);
            uint32_t h0, l0_, h1, l1_;
            split2(kv.x, kv.y, h0, l0_);
            split2(kv.z, kv.w, h1, l1_);
            KsH[r][c4 * 2] = h0; KsH[r][c4 * 2 + 1] = h1;
            KsL[r][c4 * 2] = l0_; KsL[r][c4 * 2 + 1] = l1_;
        }
        // ---- V chunk: split + transpose to [dim][key-pair] ----
        {
            int d0 = (tid >> 4) * 4;          // 0..60
            #pragma unroll
            for (int l = 0; l < 2; l++) {
                int jp = (tid & 15) + 16 * l; // 0..31
                int j = j0 + 2 * jp;
                float4 va = make_float4(0.f, 0.f, 0.f, 0.f);
                float4 vb = va;
                const float* p = g_qkv + base + (size_t)j * QKVW + 2 * DMODEL + h * 64 + d0;
                if (j < NTOK)     va = *(const float4*)(p);
                if (j + 1 < NTOK) vb = *(const float4*)(p + QKVW);
                uint32_t hh, ll;
                split2(va.x, vb.x, hh, ll); VsH[d0 + 0][jp] = hh; VsL[d0 + 0][jp] = ll;
                split2(va.y, vb.y, hh, ll); VsH[d0 + 1][jp] = hh; VsL[d0 + 1][jp] = ll;
                split2(va.z, vb.z, hh, ll); VsH[d0 + 2][jp] = hh; VsL[d0 + 2][jp] = ll;
                split2(va.w, vb.w, hh, ll); VsH[d0 + 3][jp] = hh; VsL[d0 + 3][jp] = ll;
            }
        }
        __syncthreads();

        // ---- S = Q K^T (scaled, log2 domain) ----
        float S[8][4];
        #pragma unroll
        for (int nj = 0; nj < 8; nj++)
            #pragma unroll
            for (int q = 0; q < 4; q++) S[nj][q] = 0.f;

        #pragma unroll
        for (int kk = 0; kk < 4; kk++) {
            int kc = kk * 8;
            #pragma unroll
            for (int nj = 0; nj < 8; nj++) {
                int nc = 8 * nj + g;
                uint32_t kb[2], kl[2];
                kb[0] = KsH[nc][kc + t]; kb[1] = KsH[nc][kc + t + 4];
                kl[0] = KsL[nc][kc + t]; kl[1] = KsL[nc][kc + t + 4];
                mma_bf16(S[nj], qh[kk], kb);
                mma_bf16(S[nj], ql[kk], kb);
                mma_bf16(S[nj], qh[kk], kl);
            }
        }

        // ---- mask invalid keys (only last chunk) ----
        if (j0 + 64 > NTOK) {
            #pragma unroll
            for (int nj = 0; nj < 8; nj++) {
                int col = j0 + 8 * nj + 2 * t;
                if (col >= NTOK)     { S[nj][0] = -1e30f; S[nj][2] = -1e30f; }
                if (col + 1 >= NTOK) { S[nj][1] = -1e30f; S[nj][3] = -1e30f; }
            }
        }

        // ---- online softmax (log2 domain) ----
        float cm0 = -1e30f, cm1 = -1e30f;
        #pragma unroll
        for (int nj = 0; nj < 8; nj++) {
            cm0 = fmaxf(cm0, fmaxf(S[nj][0], S[nj][1]));
            cm1 = fmaxf(cm1, fmaxf(S[nj][2], S[nj][3]));
        }
        cm0 = fmaxf(cm0, __shfl_xor_sync(0xffffffffu, cm0, 1));
        cm0 = fmaxf(cm0, __shfl_xor_sync(0xffffffffu, cm0, 2));
        cm1 = fmaxf(cm1, __shfl_xor_sync(0xffffffffu, cm1, 1));
        cm1 = fmaxf(cm1, __shfl_xor_sync(0xffffffffu, cm1, 2));
        float mn0 = fmaxf(mr0, cm0), mn1 = fmaxf(mr1, cm1);
        float f0 = exp2f(mr0 - mn0), f1 = exp2f(mr1 - mn1);
        float ps0 = 0.f, ps1 = 0.f;
        #pragma unroll
        for (int nj = 0; nj < 8; nj++) {
            S[nj][0] = exp2f(S[nj][0] - mn0);
            S[nj][1] = exp2f(S[nj][1] - mn0);
            S[nj][2] = exp2f(S[nj][2] - mn1);
            S[nj][3] = exp2f(S[nj][3] - mn1);
            ps0 += S[nj][0] + S[nj][1];
            ps1 += S[nj][2] + S[nj][3];
        }
        ps0 += __shfl_xor_sync(0xffffffffu, ps0, 1);
        ps0 += __shfl_xor_sync(0xffffffffu, ps0, 2);
        ps1 += __shfl_xor_sync(0xffffffffu, ps1, 1);
        ps1 += __shfl_xor_sync(0xffffffffu, ps1, 2);
        lr0 = lr0 * f0 + ps0;
        lr1 = lr1 * f1 + ps1;
        mr0 = mn0; mr1 = mn1;
        #pragma unroll
        for (int nj = 0; nj < 8; nj++) {
            O[nj][0] *= f0; O[nj][1] *= f0;
            O[nj][2] *= f1; O[nj][3] *= f1;
        }

        // ---- O += P @ V (V fragments straight from smem) ----
        #pragma unroll
        for (int kk = 0; kk < 4; kk++) {
            int j2 = 2 * kk;
            uint32_t ph[4], pl[4];
            split2(S[j2][0],     S[j2][1],     ph[0], pl[0]);
            split2(S[j2][2],     S[j2][3],     ph[1], pl[1]);
            split2(S[j2 + 1][0], S[j2 + 1][1], ph[2], pl[2]);
            split2(S[j2 + 1][2], S[j2 + 1][3], ph[3], pl[3]);
            #pragma unroll
            for (int nj = 0; nj < 8; nj++) {
                int n = 8 * nj + g;
                uint32_t vh[2], vl[2];
                vh[0] = VsH[n][8 * kk + t]; vh[1] = VsH[n][8 * kk + t + 4];
                vl[0] = VsL[n][8 * kk + t]; vl[1] = VsL[n][8 * kk + t + 4];
                mma_bf16(O[nj], ph, vh);
                mma_bf16(O[nj], pl, vh);
                mma_bf16(O[nj], ph, vl);
            }
        }
    }

    // ---- write out ----
    float i0 = 1.f / lr0, i1 = 1.f / lr1;
    float* o0 = g_ctx + ((size_t)b * NTOK + row0 + g) * DMODEL + h * 64;
    float* o1 = g_ctx + ((size_t)b * NTOK + row0 + g + 8) * DMODEL + h * 64;
    #pragma unroll
    for (int nj = 0; nj < 8; nj++) {
        int col = 8 * nj + 2 * t;
        *(float2*)(o0 + col) = make_float2(O[nj][0] * i0, O[nj][1] * i0);
        *(float2*)(o1 + col) = make_float2(O[nj][2] * i1, O[nj][3] * i1);
    }
}

// ---------------- block reduction helpers (256 threads) ----------------
__device__ __forceinline__ float blockReduceSum(float v, float* red) {
    #pragma unroll
    for (int o = 16; o > 0; o >>= 1) v += __shfl_xor_sync(0xffffffffu, v, o);
    int lane = threadIdx.x & 31, w = threadIdx.x >> 5;
    __syncthreads();
    if (lane == 0) red[w] = v;
    __syncthreads();
    if (threadIdx.x == 0) {
        float s = 0.f;
        #pragma unroll
        for (int i = 0; i < 8; i++) s += red[i];
        red[0] = s;
    }
    __syncthreads();
    return red[0];
}

__device__ __forceinline__ float blockReduceMax(float v, float* red) {
    #pragma unroll
    for (int o = 16; o > 0; o >>= 1) v = fmaxf(v, __shfl_xor_sync(0xffffffffu, v, o));
    int lane = threadIdx.x & 31, w = threadIdx.x >> 5;
    __syncthreads();
    if (lane == 0) red[w] = v;
    __syncthreads();
    if (threadIdx.x == 0) {
        float s = -1e30f;
        #pragma unroll
        for (int i = 0; i < 8; i++) s = fmaxf(s, red[i]);
        red[0] = s;
    }
    __syncthreads();
    return red[0];
}

// ---------------- LayerNorm ----------------
__global__ __launch_bounds__(256) void ln_kernel(const float* __restrict__ x,
                                                 const float* __restrict__ w,
                                                 const float* __restrict__ bias) {
    int row = blockIdx.x;
    const float* xr = x + (size_t)row * DMODEL;
    int t = threadIdx.x;
    float v[3];
    float s = 0.f, sq = 0.f;
    #pragma unroll
    for (int i = 0; i < 3; i++) {
        v[i] = xr[t + i * 256];
        s += v[i];
        sq += v[i] * v[i];
    }
    __shared__ float red[32];
    __shared__ float stats[2];
    #pragma unroll
    for (int o = 16; o > 0; o >>= 1) {
        s  += __shfl_xor_sync(0xffffffffu, s, o);
        sq += __shfl_xor_sync(0xffffffffu, sq, o);
    }
    int lane = t & 31, wp = t >> 5;
    if (lane == 0) { red[wp] = s; red[8 + wp] = sq; }
    __syncthreads();
    if (t == 0) {
        float a = 0.f, b2 = 0.f;
        #pragma unroll
        for (int i = 0; i < 8; i++) { a += red[i]; b2 += red[8 + i]; }
        stats[0] = a; stats[1] = b2;
    }
    __syncthreads();
    float mean = stats[0] * (1.f / DMODEL);
    float var  = stats[1] * (1.f / DMODEL) - mean * mean;
    float inv  = rsqrtf(var + EPS);
    float* o = g_xnorm + (size_t)row * DMODEL;
    #pragma unroll
    for (int i = 0; i < 3; i++) {
        int c = t + i * 256;
        o[c] = (v[i] - mean) * inv * w[c] + bias[c];
    }
}

// ---------------- CLS row (query row 0) ----------------
__global__ __launch_bounds__(256) void cls_kernel(const float* __restrict__ canny,
                                                  const float* __restrict__ noise) {
    int bh = blockIdx.x;
    int b = bh / NH, h = bh % NH;
    __shared__ float sm[NTOK];
    __shared__ float q0[64];
    __shared__ float red[32];
    __shared__ float part[4][64];
    int tid = threadIdx.x;
    size_t base = (size_t)b * NTOK * QKVW;

    if (tid < 64) q0[tid] = g_qkv[base + h * 64 + tid];
    __syncthreads();

    for (int j = tid; j < NTOK; j += 256) {
        const float* kp = g_qkv + base + (size_t)j * QKVW + DMODEL + h * 64;
        float dot = 0.f;
        #pragma unroll
        for (int c4 = 0; c4 < 16; c4++) {
            float4 kv = *(const float4*)(kp + c4 * 4);
            dot += q0[c4 * 4 + 0] * kv.x + q0[c4 * 4 + 1] * kv.y
                 + q0[c4 * 4 + 2] * kv.z + q0[c4 * 4 + 3] * kv.w;
        }
        sm[j] = dot * SCALE;
    }
    __syncthreads();

    float mx = -1e30f, cs = 0.f, ns = 0.f;
    for (int j = tid; j < NPATCH; j += 256) {
        mx = fmaxf(mx, sm[j + 1]);
        cs += canny[(size_t)b * NPATCH + j] + 1.f;
        ns += noise[(size_t)b * NPATCH + j];
    }
    mx = blockReduceMax(mx, red);
    cs = blockReduceSum(cs, red);
    ns = blockReduceSum(ns, red);
    float se = 0.f;
    for (int j = tid; j < NPATCH; j += 256) se += exp2f((sm[j + 1] - mx) * LOG2E);
    se = blockReduceSum(se, red);
    float inv_se = 1.f / se, inv_cs = 1.f / cs, inv_ns = 1.f / ns;
    for (int j = tid; j < NPATCH; j += 256) {
        float a = exp2f((sm[j + 1] - mx) * LOG2E) * inv_se;
        sm[j + 1] = a + (canny[(size_t)b * NPATCH + j] + 1.f) * inv_cs
                      + noise[(size_t)b * NPATCH + j] * inv_ns;
    }
    __syncthreads();

    float mx2 = -1e30f;
    for (int j = tid; j < NTOK; j += 256) mx2 = fmaxf(mx2, sm[j]);
    mx2 = blockReduceMax(mx2, red);
    float se2 = 0.f;
    for (int j = tid; j < NTOK; j += 256) se2 += exp2f((sm[j] - mx2) * LOG2E);
    se2 = blockReduceSum(se2, red);
    float inv2 = 1.f / se2;
    for (int j = tid; j < NTOK; j += 256) sm[j] = exp2f((sm[j] - mx2) * LOG2E) * inv2;
    __syncthreads();

    int d = tid & 63, qp = tid >> 6;
    float acc = 0.f;
    for (int j = qp; j < NTOK; j += 4)
        acc += sm[j] * g_qkv[base + (size_t)j * QKVW + 2 * DMODEL + h * 64 + d];
    part[qp][d] = acc;
    __syncthreads();
    if (tid < 64) {
        float o = part[0][tid] + part[1][tid] + part[2][tid] + part[3][tid];
        g_ctx[(size_t)b * NTOK * DMODEL + h * 64 + tid] = o;
    }
}

// ---------------- launch ----------------
extern "C" void kernel_launch(void* const* d_in, const int* in_sizes, int n_in,
                              void* d_out, int out_size) {
    const float* x     = (const float*)d_in[0];
    const float* canny = (const float*)d_in[1];
    const float* noise = (const float*)d_in[2];
    const float* ln_w  = (const float*)d_in[3];
    const float* ln_b  = (const float*)d_in[4];
    const float* w_qkv = (const float*)d_in[5];
    const float* w_out = (const float*)d_in[6];
    const float* b_out = (const float*)d_in[7];
    float* out = (float*)d_out;

    float* wqkvT = nullptr;
    float* woutT = nullptr;
    cudaGetSymbolAddress((void**)&wqkvT, g_wqkvT);
    cudaGetSymbolAddress((void**)&woutT, g_woutT);

    // 1. LayerNorm
    ln_kernel<<<MTOT, 256>>>(x, ln_w, ln_b);

    // 1b. transpose weights to [N, K]
    {
        dim3 g1(QKVW / 32, DMODEL / 32);
        transpose_kernel<<<g1, 256>>>(w_qkv, wqkvT, DMODEL, QKVW);
        dim3 g2(DMODEL / 32, DMODEL / 32);
        transpose_kernel<<<g2, 256>>>(w_out, woutT, DMODEL, DMODEL);
    }

    // 2. QKV GEMM: [8200,768] @ [768,2304] -> g_qkv
    {
        dim3 grid(QKVW / 128, (MTOT + 127) / 128);
        gemm_mma<0><<<grid, 256>>>(wqkvT, nullptr, nullptr, MTOT, QKVW, DMODEL);
    }

    // 3. attention rows 1..1024 (tensor-core flash, 128 q rows/block)
    {
        dim3 g_attn(8, BATCH * NH);
        attn_mma_kernel<<<g_attn, 256>>>();
    }

    // 4. CLS row with prior injection
    cls_kernel<<<BATCH * NH, 256>>>(canny, noise);

    // 5. output projection: [8200,768] @ [768,768] + b_out -> d_out
    {
        dim3 grid(DMODEL / 128, (MTOT + 127) / 128);
        gemm_mma<1><<<grid, 256>>>(woutT, b_out, out, MTOT, DMODEL, DMODEL);
    }
}

// round 7
// speedup vs baseline: 3.1017x; 1.0124x over previous
#include <cuda_runtime.h>
#include <cuda_bf16.h>
#include <math.h>
#include <stdint.h>

#define BATCH   8
#define NTOK    1025
#define DMODEL  768
#define NH      12
#define HDIM    64
#define NPATCH  1024
#define QKVW    (3*DMODEL)          // 2304
#define EPS     1e-5f
#define LOG2E   1.4426950408889634f
#define SCALE   0.03608439182435161f   // 768^-0.5
#define MTOT    (BATCH*NTOK)        // 8200

// ---------------- scratch (device globals; no allocation) ----------------
__device__ __nv_bfloat16 g_xn_hi [(size_t)MTOT * DMODEL];
__device__ __nv_bfloat16 g_xn_lo [(size_t)MTOT * DMODEL];
__device__ __nv_bfloat16 g_qkv_hi[(size_t)MTOT * QKVW];
__device__ __nv_bfloat16 g_qkv_lo[(size_t)MTOT * QKVW];
__device__ __nv_bfloat16 g_ctx_hi[(size_t)MTOT * DMODEL];
__device__ __nv_bfloat16 g_ctx_lo[(size_t)MTOT * DMODEL];
__device__ __nv_bfloat16 g_wqkvT_hi[(size_t)QKVW * DMODEL];
__device__ __nv_bfloat16 g_wqkvT_lo[(size_t)QKVW * DMODEL];
__device__ __nv_bfloat16 g_woutT_hi[(size_t)DMODEL * DMODEL];
__device__ __nv_bfloat16 g_woutT_lo[(size_t)DMODEL * DMODEL];

// ---------------- helpers ----------------
__device__ __forceinline__ uint32_t smem_u32(const void* p) {
    uint32_t a;
    asm("{ .reg .u64 t; cvta.to.shared.u64 t, %1; cvt.u32.u64 %0, t; }" : "=r"(a) : "l"(p));
    return a;
}

__device__ __forceinline__ void mma_bf16(float* c, const uint32_t* a, const uint32_t* b) {
    asm volatile(
        "mma.sync.aligned.m16n8k16.row.col.f32.bf16.bf16.f32 "
        "{%0,%1,%2,%3}, {%4,%5,%6,%7}, {%8,%9}, {%0,%1,%2,%3};"
        : "+f"(c[0]), "+f"(c[1]), "+f"(c[2]), "+f"(c[3])
        : "r"(a[0]), "r"(a[1]), "r"(a[2]), "r"(a[3]), "r"(b[0]), "r"(b[1]));
}

__device__ __forceinline__ void ldsm_x4(uint32_t* f, uint32_t addr) {
    asm volatile("ldmatrix.sync.aligned.m8n8.x4.shared.b16 {%0,%1,%2,%3}, [%4];"
        : "=r"(f[0]), "=r"(f[1]), "=r"(f[2]), "=r"(f[3]) : "r"(addr));
}
__device__ __forceinline__ void ldsm_x2(uint32_t* f, uint32_t addr) {
    asm volatile("ldmatrix.sync.aligned.m8n8.x2.shared.b16 {%0,%1}, [%2];"
        : "=r"(f[0]), "=r"(f[1]) : "r"(addr));
}

#define CP_ASYNC16(dst, src, nbytes) \
    asm volatile("cp.async.cg.shared.global [%0], [%1], 16, %2;" \
                 :: "r"(dst), "l"(src), "r"(nbytes))
#define CP_COMMIT() asm volatile("cp.async.commit_group;")
#define CP_WAIT1()  asm volatile("cp.async.wait_group 1;")
#define CP_WAIT0()  asm volatile("cp.async.wait_group 0;")

// hi/lo bf16 split of two floats -> packed bf16x2 (hi, lo); a in low half
__device__ __forceinline__ void split2(float a, float b, uint32_t& hp, uint32_t& lp) {
    __nv_bfloat16 ha = __float2bfloat16_rn(a), hb = __float2bfloat16_rn(b);
    float ra = a - __bfloat162float(ha), rb = b - __bfloat162float(hb);
    __nv_bfloat16 la = __float2bfloat16_rn(ra), lb = __float2bfloat16_rn(rb);
    hp = (uint32_t)__bfloat16_as_ushort(ha) | ((uint32_t)__bfloat16_as_ushort(hb) << 16);
    lp = (uint32_t)__bfloat16_as_ushort(la) | ((uint32_t)__bfloat16_as_ushort(lb) << 16);
}

// ---------------- weight transpose + split: dst[N,K] = split(src[K,N]) ----------------
__global__ __launch_bounds__(256) void transpose_split_kernel(const float* __restrict__ src,
                                                              __nv_bfloat16* __restrict__ dh,
                                                              __nv_bfloat16* __restrict__ dl,
                                                              int K, int N) {
    __shared__ float t[32][33];
    int nx = blockIdx.x * 32, kx = blockIdx.y * 32;
    int lx = threadIdx.x & 31, ly = threadIdx.x >> 5;
    #pragma unroll
    for (int i = ly; i < 32; i += 8)
        t[i][lx] = src[(size_t)(kx + i) * N + nx + lx];
    __syncthreads();
    #pragma unroll
    for (int i = ly; i < 32; i += 8) {
        float v = t[lx][i];
        __nv_bfloat16 h = __float2bfloat16_rn(v);
        size_t o = (size_t)(nx + i) * K + kx + lx;
        dh[o] = h;
        dl[o] = __float2bfloat16_rn(v - __bfloat162float(h));
    }
}

// ================= tensor-core GEMM (cp.async double-buffered) =================
// C[M,N] = A[M,K] @ Bt[N,K]^T, A/B pre-split bf16 hi/lo in gmem.
// SEL=0: A=g_xn, C=g_qkv_hi/lo (split store). SEL=1: A=g_ctx, C=Cext fp32 (+bias).
#define SM_STRIDE 20
#define ARR_BYTES (128 * SM_STRIDE * 4)     // 10240
#define STG_BYTES (4 * ARR_BYTES)           // 40960
#define GEMM_SMEM (2 * STG_BYTES)           // 81920

template<int SEL>
__global__ __launch_bounds__(256) void gemm_mma(const __nv_bfloat16* __restrict__ Bh,
                                                const __nv_bfloat16* __restrict__ Bl,
                                                const float* __restrict__ bias,
                                                float* __restrict__ Cext,
                                                int M, int N, int K) {
    const __nv_bfloat16* Ah = (SEL == 0) ? g_xn_hi : g_ctx_hi;
    const __nv_bfloat16* Al = (SEL == 0) ? g_xn_lo : g_ctx_lo;

    extern __shared__ char smem[];
    uint32_t sbase = smem_u32(smem);

    int tid = threadIdx.x;
    int wid = tid >> 5, lane = tid & 31;
    int g = lane >> 2, t = lane & 3;
    int wm = wid & 1, wn = wid >> 1;
    int m0 = blockIdx.y * 128, n0 = blockIdx.x * 128;
    int mw = wm * 64, nw = wn * 32;

    // ldmatrix per-lane offsets (bytes)
    int rA = (lane & 7) + ((lane >> 3) & 1) * 8;
    int cA = (lane >> 4) * 4;
    uint32_t aoff = (uint32_t)(rA * SM_STRIDE + cA) * 4u;
    int rB = lane & 7;
    int cB = ((lane >> 3) & 1) * 4;
    uint32_t boff = (uint32_t)(rB * SM_STRIDE + cB) * 4u;

    // loader mapping: idx -> row r = idx>>2, quarter q = idx&3 (16B each)
    int lr = tid >> 2, lq = tid & 3;

    float acc[4][4][4];
    #pragma unroll
    for (int i = 0; i < 4; i++)
        #pragma unroll
        for (int j = 0; j < 4; j++)
            #pragma unroll
            for (int q = 0; q < 4; q++) acc[i][j][q] = 0.f;

    int nch = K / 32;

    // stage loader: 8 cp.async per thread (2 row-halves x 4 arrays)
    auto load_stage = [&](int ch, int s) {
        int kb = ch * 32;
        uint32_t so = sbase + (uint32_t)s * STG_BYTES;
        #pragma unroll
        for (int l = 0; l < 2; l++) {
            int r = lr + l * 64;
            uint32_t d = (uint32_t)(r * SM_STRIDE + lq * 4) * 4u;
            int okA = (m0 + r < M) ? 16 : 0;
            size_t ao = (size_t)(m0 + r) * K + kb + lq * 8;
            size_t bo = (size_t)(n0 + r) * K + kb + lq * 8;
            CP_ASYNC16(so + d,                 Ah + ao, okA);
            CP_ASYNC16(so + ARR_BYTES + d,     Al + ao, okA);
            CP_ASYNC16(so + 2 * ARR_BYTES + d, Bh + bo, 16);
            CP_ASYNC16(so + 3 * ARR_BYTES + d, Bl + bo, 16);
        }
    };

    load_stage(0, 0);
    CP_COMMIT();

    for (int ch = 0; ch < nch; ch++) {
        int s = ch & 1;
        if (ch + 1 < nch) {
            load_stage(ch + 1, s ^ 1);
            CP_COMMIT();
            CP_WAIT1();
        } else {
            CP_WAIT0();
        }
        __syncthreads();

        uint32_t uAH = sbase + (uint32_t)s * STG_BYTES;
        uint32_t uAL = uAH + ARR_BYTES;
        uint32_t uBH = uAH + 2 * ARR_BYTES;
        uint32_t uBL = uAH + 3 * ARR_BYTES;

        #pragma unroll
        for (int kk = 0; kk < 2; kk++) {
            uint32_t kcb = (uint32_t)(kk * 8) * 4u;
            uint32_t ah[4][4], al[4][4];
            #pragma unroll
            for (int mi = 0; mi < 4; mi++) {
                uint32_t base = (uint32_t)((mw + mi * 16) * SM_STRIDE) * 4u + kcb + aoff;
                ldsm_x4(ah[mi], uAH + base);
                ldsm_x4(al[mi], uAL + base);
            }
            uint32_t bh[4][2], bl[4][2];
            #pragma unroll
            for (int nj = 0; nj < 4; nj++) {
                uint32_t base = (uint32_t)((nw + nj * 8) * SM_STRIDE) * 4u + kcb + boff;
                ldsm_x2(bh[nj], uBH + base);
                ldsm_x2(bl[nj], uBL + base);
            }
            #pragma unroll
            for (int mi = 0; mi < 4; mi++)
                #pragma unroll
                for (int nj = 0; nj < 4; nj++) {
                    mma_bf16(acc[mi][nj], ah[mi], bh[nj]);
                    mma_bf16(acc[mi][nj], al[mi], bh[nj]);
                    mma_bf16(acc[mi][nj], ah[mi], bl[nj]);
                }
        }
        __syncthreads();
    }

    // ---- epilogue ----
    #pragma unroll
    for (int mi = 0; mi < 4; mi++) {
        int r0e = m0 + mw + mi * 16 + g;
        #pragma unroll
        for (int nj = 0; nj < 4; nj++) {
            int col = n0 + nw + nj * 8 + t * 2;
            if (SEL == 0) {
                #pragma unroll
                for (int half = 0; half < 2; half++) {
                    int row = r0e + half * 8;
                    if (row < M) {
                        uint32_t hp, lp;
                        split2(acc[mi][nj][2 * half], acc[mi][nj][2 * half + 1], hp, lp);
                        size_t o = (size_t)row * N + col;
                        *(uint32_t*)((char*)g_qkv_hi + o * 2) = hp;
                        *(uint32_t*)((char*)g_qkv_lo + o * 2) = lp;
                    }
                }
            } else {
                float b0 = bias[col], b1 = bias[col + 1];
                if (r0e < M)
                    *(float2*)(Cext + (size_t)r0e * N + col) =
                        make_float2(acc[mi][nj][0] + b0, acc[mi][nj][1] + b1);
                if (r0e + 8 < M)
                    *(float2*)(Cext + (size_t)(r0e + 8) * N + col) =
                        make_float2(acc[mi][nj][2] + b0, acc[mi][nj][3] + b1);
            }
        }
    }
}

// ================= tensor-core flash attention (rows 1..1024) =================
// grid (8, 96), 256 threads (8 warps x m16). K/V already bf16 hi/lo in gmem.
__global__ __launch_bounds__(256) void attn_mma_kernel() {
    int qt = blockIdx.x;
    int bh_ = blockIdx.y;
    int b = bh_ / NH, h = bh_ % NH;

    __shared__ uint32_t KsH[64][36];   // [key][dim-pair]
    __shared__ uint32_t KsL[64][36];
    __shared__ uint32_t VsH[64][36];   // [dim][key-pair]
    __shared__ uint32_t VsL[64][36];

    int tid = threadIdx.x, wid = tid >> 5, lane = tid & 31;
    int g = lane >> 2, t = lane & 3;
    size_t base = (size_t)b * NTOK * QKVW;

    // ---- Q fragments: reconstruct fp32 from hi/lo, scale, re-split ----
    int row0 = 1 + qt * 128 + wid * 16;
    const float qsc = SCALE * LOG2E;
    const __nv_bfloat16* Qh0 = g_qkv_hi + base + (size_t)(row0 + g) * QKVW + h * 64;
    const __nv_bfloat16* Ql0 = g_qkv_lo + base + (size_t)(row0 + g) * QKVW + h * 64;
    const __nv_bfloat16* Qh1 = Qh0 + 8 * QKVW;
    const __nv_bfloat16* Ql1 = Ql0 + 8 * QKVW;
    uint32_t qh[4][4], ql[4][4];
    #pragma unroll
    for (int kk = 0; kk < 4; kk++) {
        int k0 = kk * 16 + 2 * t;
        #pragma unroll
        for (int fi = 0; fi < 4; fi++) {
            int ko = k0 + (fi >> 1) * 8;
            const __nv_bfloat16* ph = (fi & 1) ? Qh1 : Qh0;
            const __nv_bfloat16* pl = (fi & 1) ? Ql1 : Ql0;
            __nv_bfloat162 vh = *(const __nv_bfloat162*)(ph + ko);
            __nv_bfloat162 vl = *(const __nv_bfloat162*)(pl + ko);
            float a = (__bfloat162float(vh.x) + __bfloat162float(vl.x)) * qsc;
            float c = (__bfloat162float(vh.y) + __bfloat162float(vl.y)) * qsc;
            split2(a, c, qh[kk][fi], ql[kk][fi]);
        }
    }

    float O[8][4];
    #pragma unroll
    for (int nj = 0; nj < 8; nj++)
        #pragma unroll
        for (int q = 0; q < 4; q++) O[nj][q] = 0.f;
    float mr0 = -1e30f, mr1 = -1e30f, lr0 = 0.f, lr1 = 0.f;

    for (int c = 0; c < 17; c++) {
        int j0 = c * 64;
        __syncthreads();
        // ---- K chunk: straight uint4 copy (64 keys x 64 dims) ----
        #pragma unroll
        for (int l = 0; l < 2; l++) {
            int idx = tid + l * 256;
            int r = idx >> 3, c8 = idx & 7;
            int j = j0 + r;
            uint4 vh = make_uint4(0, 0, 0, 0), vl = vh;
            if (j < NTOK) {
                size_t o = base + (size_t)j * QKVW + DMODEL + h * 64 + c8 * 8;
                vh = *(const uint4*)((const char*)g_qkv_hi + o * 2);
                vl = *(const uint4*)((const char*)g_qkv_lo + o * 2);
            }
            *(uint4*)&KsH[r][c8 * 4] = vh;
            *(uint4*)&KsL[r][c8 * 4] = vl;
        }
        // ---- V chunk: repack to [dim][key-pair] via byte_perm ----
        {
            int d0 = (tid >> 4) * 4;
            #pragma unroll
            for (int l = 0; l < 2; l++) {
                int jp = (tid & 15) + 16 * l;
                int j = j0 + 2 * jp;
                uint2 ah = make_uint2(0, 0), bh2 = ah, al = ah, bl = ah;
                size_t o = base + (size_t)j * QKVW + 2 * DMODEL + h * 64 + d0;
                if (j < NTOK) {
                    ah = *(const uint2*)((const char*)g_qkv_hi + o * 2);
                    al = *(const uint2*)((const char*)g_qkv_lo + o * 2);
                }
                if (j + 1 < NTOK) {
                    bh2 = *(const uint2*)((const char*)g_qkv_hi + (o + QKVW) * 2);
                    bl  = *(const uint2*)((const char*)g_qkv_lo + (o + QKVW) * 2);
                }
                VsH[d0 + 0][jp] = __byte_perm(ah.x, bh2.x, 0x5410);
                VsH[d0 + 1][jp] = __byte_perm(ah.x, bh2.x, 0x7632);
                VsH[d0 + 2][jp] = __byte_perm(ah.y, bh2.y, 0x5410);
                VsH[d0 + 3][jp] = __byte_perm(ah.y, bh2.y, 0x7632);
                VsL[d0 + 0][jp] = __byte_perm(al.x, bl.x, 0x5410);
                VsL[d0 + 1][jp] = __byte_perm(al.x, bl.x, 0x7632);
                VsL[d0 + 2][jp] = __byte_perm(al.y, bl.y, 0x5410);
                VsL[d0 + 3][jp] = __byte_perm(al.y, bl.y, 0x7632);
            }
        }
        __syncthreads();

        // ---- S = Q K^T ----
        float S[8][4];
        #pragma unroll
        for (int nj = 0; nj < 8; nj++)
            #pragma unroll
            for (int q = 0; q < 4; q++) S[nj][q] = 0.f;

        #pragma unroll
        for (int kk = 0; kk < 4; kk++) {
            int kc = kk * 8;
            #pragma unroll
            for (int nj = 0; nj < 8; nj++) {
                int nc = 8 * nj + g;
                uint32_t kb[2], kl[2];
                kb[0] = KsH[nc][kc + t]; kb[1] = KsH[nc][kc + t + 4];
                kl[0] = KsL[nc][kc + t]; kl[1] = KsL[nc][kc + t + 4];
                mma_bf16(S[nj], qh[kk], kb);
                mma_bf16(S[nj], ql[kk], kb);
                mma_bf16(S[nj], qh[kk], kl);
            }
        }

        if (j0 + 64 > NTOK) {
            #pragma unroll
            for (int nj = 0; nj < 8; nj++) {
                int col = j0 + 8 * nj + 2 * t;
                if (col >= NTOK)     { S[nj][0] = -1e30f; S[nj][2] = -1e30f; }
                if (col + 1 >= NTOK) { S[nj][1] = -1e30f; S[nj][3] = -1e30f; }
            }
        }

        // ---- online softmax (log2 domain) ----
        float cm0 = -1e30f, cm1 = -1e30f;
        #pragma unroll
        for (int nj = 0; nj < 8; nj++) {
            cm0 = fmaxf(cm0, fmaxf(S[nj][0], S[nj][1]));
            cm1 = fmaxf(cm1, fmaxf(S[nj][2], S[nj][3]));
        }
        cm0 = fmaxf(cm0, __shfl_xor_sync(0xffffffffu, cm0, 1));
        cm0 = fmaxf(cm0, __shfl_xor_sync(0xffffffffu, cm0, 2));
        cm1 = fmaxf(cm1, __shfl_xor_sync(0xffffffffu, cm1, 1));
        cm1 = fmaxf(cm1, __shfl_xor_sync(0xffffffffu, cm1, 2));
        float mn0 = fmaxf(mr0, cm0), mn1 = fmaxf(mr1, cm1);
        float f0 = exp2f(mr0 - mn0), f1 = exp2f(mr1 - mn1);
        float ps0 = 0.f, ps1 = 0.f;
        #pragma unroll
        for (int nj = 0; nj < 8; nj++) {
            S[nj][0] = exp2f(S[nj][0] - mn0);
            S[nj][1] = exp2f(S[nj][1] - mn0);
            S[nj][2] = exp2f(S[nj][2] - mn1);
            S[nj][3] = exp2f(S[nj][3] - mn1);
            ps0 += S[nj][0] + S[nj][1];
            ps1 += S[nj][2] + S[nj][3];
        }
        ps0 += __shfl_xor_sync(0xffffffffu, ps0, 1);
        ps0 += __shfl_xor_sync(0xffffffffu, ps0, 2);
        ps1 += __shfl_xor_sync(0xffffffffu, ps1, 1);
        ps1 += __shfl_xor_sync(0xffffffffu, ps1, 2);
        lr0 = lr0 * f0 + ps0;
        lr1 = lr1 * f1 + ps1;
        mr0 = mn0; mr1 = mn1;
        #pragma unroll
        for (int nj = 0; nj < 8; nj++) {
            O[nj][0] *= f0; O[nj][1] *= f0;
            O[nj][2] *= f1; O[nj][3] *= f1;
        }

        // ---- O += P @ V ----
        #pragma unroll
        for (int kk = 0; kk < 4; kk++) {
            int j2 = 2 * kk;
            uint32_t ph[4], pl[4];
            split2(S[j2][0],     S[j2][1],     ph[0], pl[0]);
            split2(S[j2][2],     S[j2][3],     ph[1], pl[1]);
            split2(S[j2 + 1][0], S[j2 + 1][1], ph[2], pl[2]);
            split2(S[j2 + 1][2], S[j2 + 1][3], ph[3], pl[3]);
            #pragma unroll
            for (int nj = 0; nj < 8; nj++) {
                int n = 8 * nj + g;
                uint32_t vh[2], vl[2];
                vh[0] = VsH[n][8 * kk + t]; vh[1] = VsH[n][8 * kk + t + 4];
                vl[0] = VsL[n][8 * kk + t]; vl[1] = VsL[n][8 * kk + t + 4];
                mma_bf16(O[nj], ph, vh);
                mma_bf16(O[nj], pl, vh);
                mma_bf16(O[nj], ph, vl);
            }
        }
    }

    // ---- write out (split to g_ctx hi/lo) ----
    float i0 = 1.f / lr0, i1 = 1.f / lr1;
    size_t o0 = ((size_t)b * NTOK + row0 + g) * DMODEL + h * 64;
    size_t o1 = o0 + (size_t)8 * DMODEL;
    #pragma unroll
    for (int nj = 0; nj < 8; nj++) {
        int col = 8 * nj + 2 * t;
        uint32_t hp, lp;
        split2(O[nj][0] * i0, O[nj][1] * i0, hp, lp);
        *(uint32_t*)((char*)g_ctx_hi + (o0 + col) * 2) = hp;
        *(uint32_t*)((char*)g_ctx_lo + (o0 + col) * 2) = lp;
        split2(O[nj][2] * i1, O[nj][3] * i1, hp, lp);
        *(uint32_t*)((char*)g_ctx_hi + (o1 + col) * 2) = hp;
        *(uint32_t*)((char*)g_ctx_lo + (o1 + col) * 2) = lp;
    }
}

// ---------------- block reduction helpers ----------------
__device__ __forceinline__ float blockReduceSum(float v, float* red) {
    #pragma unroll
    for (int o = 16; o > 0; o >>= 1) v += __shfl_xor_sync(0xffffffffu, v, o);
    int lane = threadIdx.x & 31, w = threadIdx.x >> 5;
    __syncthreads();
    if (lane == 0) red[w] = v;
    __syncthreads();
    if (threadIdx.x == 0) {
        float s = 0.f;
        #pragma unroll
        for (int i = 0; i < 8; i++) s += red[i];
        red[0] = s;
    }
    __syncthreads();
    return red[0];
}

__device__ __forceinline__ float blockReduceMax(float v, float* red) {
    #pragma unroll
    for (int o = 16; o > 0; o >>= 1) v = fmaxf(v, __shfl_xor_sync(0xffffffffu, v, o));
    int lane = threadIdx.x & 31, w = threadIdx.x >> 5;
    __syncthreads();
    if (lane == 0) red[w] = v;
    __syncthreads();
    if (threadIdx.x == 0) {
        float s = -1e30f;
        #pragma unroll
        for (int i = 0; i < 8; i++) s = fmaxf(s, red[i]);
        red[0] = s;
    }
    __syncthreads();
    return red[0];
}

// ---------------- LayerNorm -> split bf16 hi/lo ----------------
__global__ __launch_bounds__(256) void ln_kernel(const float* __restrict__ x,
                                                 const float* __restrict__ w,
                                                 const float* __restrict__ bias) {
    int row = blockIdx.x;
    const float* xr = x + (size_t)row * DMODEL;
    int t = threadIdx.x;
    float v[3];
    float s = 0.f, sq = 0.f;
    #pragma unroll
    for (int i = 0; i < 3; i++) {
        v[i] = xr[t + i * 256];
        s += v[i];
        sq += v[i] * v[i];
    }
    __shared__ float red[32];
    __shared__ float stats[2];
    #pragma unroll
    for (int o = 16; o > 0; o >>= 1) {
        s  += __shfl_xor_sync(0xffffffffu, s, o);
        sq += __shfl_xor_sync(0xffffffffu, sq, o);
    }
    int lane = t & 31, wp = t >> 5;
    if (lane == 0) { red[wp] = s; red[8 + wp] = sq; }
    __syncthreads();
    if (t == 0) {
        float a = 0.f, b2 = 0.f;
        #pragma unroll
        for (int i = 0; i < 8; i++) { a += red[i]; b2 += red[8 + i]; }
        stats[0] = a; stats[1] = b2;
    }
    __syncthreads();
    float mean = stats[0] * (1.f / DMODEL);
    float var  = stats[1] * (1.f / DMODEL) - mean * mean;
    float inv  = rsqrtf(var + EPS);
    #pragma unroll
    for (int i = 0; i < 3; i++) {
        int c = t + i * 256;
        float o = (v[i] - mean) * inv * w[c] + bias[c];
        __nv_bfloat16 h = __float2bfloat16_rn(o);
        size_t idx = (size_t)row * DMODEL + c;
        g_xn_hi[idx] = h;
        g_xn_lo[idx] = __float2bfloat16_rn(o - __bfloat162float(h));
    }
}

// ---------------- CLS row (query row 0) ----------------
__global__ __launch_bounds__(256) void cls_kernel(const float* __restrict__ canny,
                                                  const float* __restrict__ noise) {
    int bh = blockIdx.x;
    int b = bh / NH, h = bh % NH;
    __shared__ float sm[NTOK];
    __shared__ float q0[64];
    __shared__ float red[32];
    __shared__ float part[4][64];
    int tid = threadIdx.x;
    size_t base = (size_t)b * NTOK * QKVW;

    if (tid < 64)
        q0[tid] = __bfloat162float(g_qkv_hi[base + h * 64 + tid])
                + __bfloat162float(g_qkv_lo[base + h * 64 + tid]);
    __syncthreads();

    for (int j = tid; j < NTOK; j += 256) {
        size_t ko = base + (size_t)j * QKVW + DMODEL + h * 64;
        float dot = 0.f;
        #pragma unroll
        for (int d2 = 0; d2 < 32; d2++) {
            __nv_bfloat162 kh = *(const __nv_bfloat162*)(g_qkv_hi + ko + 2 * d2);
            __nv_bfloat162 kl = *(const __nv_bfloat162*)(g_qkv_lo + ko + 2 * d2);
            dot += q0[2 * d2]     * (__bfloat162float(kh.x) + __bfloat162float(kl.x))
                 + q0[2 * d2 + 1] * (__bfloat162float(kh.y) + __bfloat162float(kl.y));
        }
        sm[j] = dot * SCALE;
    }
    __syncthreads();

    float mx = -1e30f, cs = 0.f, ns = 0.f;
    for (int j = tid; j < NPATCH; j += 256) {
        mx = fmaxf(mx, sm[j + 1]);
        cs += canny[(size_t)b * NPATCH + j] + 1.f;
        ns += noise[(size_t)b * NPATCH + j];
    }
    mx = blockReduceMax(mx, red);
    cs = blockReduceSum(cs, red);
    ns = blockReduceSum(ns, red);
    float se = 0.f;
    for (int j = tid; j < NPATCH; j += 256) se += exp2f((sm[j + 1] - mx) * LOG2E);
    se = blockReduceSum(se, red);
    float inv_se = 1.f / se, inv_cs = 1.f / cs, inv_ns = 1.f / ns;
    for (int j = tid; j < NPATCH; j += 256) {
        float a = exp2f((sm[j + 1] - mx) * LOG2E) * inv_se;
        sm[j + 1] = a + (canny[(size_t)b * NPATCH + j] + 1.f) * inv_cs
                      + noise[(size_t)b * NPATCH + j] * inv_ns;
    }
    __syncthreads();

    float mx2 = -1e30f;
    for (int j = tid; j < NTOK; j += 256) mx2 = fmaxf(mx2, sm[j]);
    mx2 = blockReduceMax(mx2, red);
    float se2 = 0.f;
    for (int j = tid; j < NTOK; j += 256) se2 += exp2f((sm[j] - mx2) * LOG2E);
    se2 = blockReduceSum(se2, red);
    float inv2 = 1.f / se2;
    for (int j = tid; j < NTOK; j += 256) sm[j] = exp2f((sm[j] - mx2) * LOG2E) * inv2;
    __syncthreads();

    int d = tid & 63, qp = tid >> 6;
    float acc = 0.f;
    for (int j = qp; j < NTOK; j += 4) {
        size_t vo = base + (size_t)j * QKVW + 2 * DMODEL + h * 64 + d;
        acc += sm[j] * (__bfloat162float(g_qkv_hi[vo]) + __bfloat162float(g_qkv_lo[vo]));
    }
    part[qp][d] = acc;
    __syncthreads();
    if (tid < 64) {
        float o = part[0][tid] + part[1][tid] + part[2][tid] + part[3][tid];
        __nv_bfloat16 hh = __float2bfloat16_rn(o);
        size_t idx = (size_t)b * NTOK * DMODEL + h * 64 + tid;
        g_ctx_hi[idx] = hh;
        g_ctx_lo[idx] = __float2bfloat16_rn(o - __bfloat162float(hh));
    }
}

// ---------------- launch ----------------
extern "C" void kernel_launch(void* const* d_in, const int* in_sizes, int n_in,
                              void* d_out, int out_size) {
    const float* x     = (const float*)d_in[0];
    const float* canny = (const float*)d_in[1];
    const float* noise = (const float*)d_in[2];
    const float* ln_w  = (const float*)d_in[3];
    const float* ln_b  = (const float*)d_in[4];
    const float* w_qkv = (const float*)d_in[5];
    const float* w_out = (const float*)d_in[6];
    const float* b_out = (const float*)d_in[7];
    float* out = (float*)d_out;

    cudaFuncSetAttribute(gemm_mma<0>, cudaFuncAttributeMaxDynamicSharedMemorySize, GEMM_SMEM);
    cudaFuncSetAttribute(gemm_mma<1>, cudaFuncAttributeMaxDynamicSharedMemorySize, GEMM_SMEM);

    __nv_bfloat16 *wqkvTh, *wqkvTl, *woutTh, *woutTl;
    cudaGetSymbolAddress((void**)&wqkvTh, g_wqkvT_hi);
    cudaGetSymbolAddress((void**)&wqkvTl, g_wqkvT_lo);
    cudaGetSymbolAddress((void**)&woutTh, g_woutT_hi);
    cudaGetSymbolAddress((void**)&woutTl, g_woutT_lo);

    // 1. LayerNorm (-> bf16 hi/lo)
    ln_kernel<<<MTOT, 256>>>(x, ln_w, ln_b);

    // 1b. transpose+split weights
    {
        dim3 g1(QKVW / 32, DMODEL / 32);
        transpose_split_kernel<<<g1, 256>>>(w_qkv, wqkvTh, wqkvTl, DMODEL, QKVW);
        dim3 g2(DMODEL / 32, DMODEL / 32);
        transpose_split_kernel<<<g2, 256>>>(w_out, woutTh, woutTl, DMODEL, DMODEL);
    }

    // 2. QKV GEMM -> g_qkv hi/lo
    {
        dim3 grid(QKVW / 128, (MTOT + 127) / 128);
        gemm_mma<0><<<grid, 256, GEMM_SMEM>>>(wqkvTh, wqkvTl, nullptr, nullptr, MTOT, QKVW, DMODEL);
    }

    // 3. attention rows 1..1024
    {
        dim3 g_attn(8, BATCH * NH);
        attn_mma_kernel<<<g_attn, 256>>>();
    }

    // 4. CLS row with prior injection
    cls_kernel<<<BATCH * NH, 256>>>(canny, noise);

    // 5. output projection -> d_out (fp32 + bias)
    {
        dim3 grid(DMODEL / 128, (MTOT + 127) / 128);
        gemm_mma<1><<<grid, 256, GEMM_SMEM>>>(woutTh, woutTl, b_out, out, MTOT, DMODEL, DMODEL);
    }
}